// round 1
// baseline (speedup 1.0000x reference)
#include <cuda_runtime.h>
#include <cstddef>

// Problem constants
#define B_SZ 16384
#define L_SZ 1024
// Tile config
#define BM 64
#define BN 128
#define BK 16
#define NTHREADS 256
#define AS_STRIDE 68    // padded row stride (floats) for As [m][l][row]
#define WS_STRIDE 130   // padded stride (u64) for Ws [l][k], 16B-aligned rows

typedef unsigned long long u64;

// Packed dual-FMA (Blackwell FFMA2): d = a*b + d lanewise on f32x2
#define FMA2(accv, av, bv) \
    asm("fma.rn.f32x2 %0, %1, %2, %0;" : "+l"(accv) : "l"(av), "l"(bv))

__global__ __launch_bounds__(NTHREADS, 1)
void fused_modal_attn_kernel(const float* __restrict__ m0,
                             const float* __restrict__ m1,
                             const float* __restrict__ m2,
                             const float* __restrict__ m3,
                             const float* __restrict__ Wm,
                             float* __restrict__ out)
{
    // A tiles transposed: [mod][l][row], rows of a pair are adjacent floats
    __shared__ __align__(16) float As[4 * BK * AS_STRIDE];
    // W tile with each scalar duplicated into both f32x2 lanes: [l][k]
    __shared__ __align__(16) u64 Ws[BK * WS_STRIDE];
    __shared__ float rsum[4 * BM];
    __shared__ float scal[BM];

    const float* mods[4] = {m0, m1, m2, m3};

    const int tid = threadIdx.x;
    const int tx = tid & 15;       // k-group: cols tx*8 .. tx*8+7
    const int ty = tid >> 4;       // row-group: rows ty*4 .. ty*4+3
    const int b0 = blockIdx.y * BM;
    const int k0 = blockIdx.x * BN;

    // Global-load mapping (per chunk): A: 4 mods x 64 rows x 16 l
    const int a_row = tid >> 2;          // 0..63
    const int a_lc  = (tid & 3) << 2;    // 0,4,8,12
    // W: 128 k x 16 l -> 2 float4 per thread, k = (tid>>2) + i*64

    u64 acc[4][8][2];   // [mod][kcol][rowpair], each holds 2 fp32 accumulators
    #pragma unroll
    for (int m = 0; m < 4; m++)
        #pragma unroll
        for (int k = 0; k < 8; k++) { acc[m][k][0] = 0ull; acc[m][k][1] = 0ull; }

    // Rowsum ownership: thread t -> (mod = t>>6, row = t&63)
    const int rs_m = tid >> 6;
    const int rs_r = tid & 63;
    float rs = 0.0f;

    float4 aReg[4];
    float4 wReg[2];

    // Prefetch chunk 0
    {
        #pragma unroll
        for (int m = 0; m < 4; m++)
            aReg[m] = *(const float4*)(mods[m] + (size_t)(b0 + a_row) * L_SZ + a_lc);
        #pragma unroll
        for (int i = 0; i < 2; i++) {
            const int k = (tid >> 2) + i * 64;
            wReg[i] = *(const float4*)(Wm + (size_t)(k0 + k) * L_SZ + a_lc);
        }
    }

    const int NCHUNK = L_SZ / BK;   // 64
    for (int c = 0; c < NCHUNK; ++c) {
        __syncthreads();   // prior chunk's smem reads done

        // Stage A (transposed) into smem
        #pragma unroll
        for (int m = 0; m < 4; m++) {
            As[(m * BK + a_lc + 0) * AS_STRIDE + a_row] = aReg[m].x;
            As[(m * BK + a_lc + 1) * AS_STRIDE + a_row] = aReg[m].y;
            As[(m * BK + a_lc + 2) * AS_STRIDE + a_row] = aReg[m].z;
            As[(m * BK + a_lc + 3) * AS_STRIDE + a_row] = aReg[m].w;
        }
        // Stage W duplicated into f32x2 pairs
        #pragma unroll
        for (int i = 0; i < 2; i++) {
            const int k = (tid >> 2) + i * 64;
            const float v[4] = {wReg[i].x, wReg[i].y, wReg[i].z, wReg[i].w};
            #pragma unroll
            for (int q = 0; q < 4; q++) {
                const unsigned bb = __float_as_uint(v[q]);
                Ws[(a_lc + q) * WS_STRIDE + k] = ((u64)bb << 32) | (u64)bb;
            }
        }
        __syncthreads();

        // Prefetch next chunk (hidden under compute below)
        if (c + 1 < NCHUNK) {
            const int l0 = (c + 1) * BK;
            #pragma unroll
            for (int m = 0; m < 4; m++)
                aReg[m] = *(const float4*)(mods[m] + (size_t)(b0 + a_row) * L_SZ + l0 + a_lc);
            #pragma unroll
            for (int i = 0; i < 2; i++) {
                const int k = (tid >> 2) + i * 64;
                wReg[i] = *(const float4*)(Wm + (size_t)(k0 + k) * L_SZ + l0 + a_lc);
            }
        }

        // Rowsum accumulation (byproduct of tile already in smem)
        #pragma unroll
        for (int l = 0; l < BK; l++)
            rs += As[(rs_m * BK + l) * AS_STRIDE + rs_r];

        // Mainloop compute: 64 FFMA2 per thread per l
        #pragma unroll
        for (int l = 0; l < BK; l++) {
            u64 a[4][2];
            #pragma unroll
            for (int m = 0; m < 4; m++) {
                const ulonglong2 av =
                    *(const ulonglong2*)(&As[(m * BK + l) * AS_STRIDE + ty * 4]);
                a[m][0] = av.x;   // rows (ty*4, ty*4+1)
                a[m][1] = av.y;   // rows (ty*4+2, ty*4+3)
            }
            u64 w[8];
            #pragma unroll
            for (int j = 0; j < 4; j++) {
                const ulonglong2 wv =
                    *(const ulonglong2*)(&Ws[l * WS_STRIDE + tx * 8 + j * 2]);
                w[j * 2]     = wv.x;
                w[j * 2 + 1] = wv.y;
            }
            #pragma unroll
            for (int m = 0; m < 4; m++)
                #pragma unroll
                for (int k = 0; k < 8; k++) {
                    FMA2(acc[m][k][0], a[m][0], w[k]);
                    FMA2(acc[m][k][1], a[m][1], w[k]);
                }
        }
    }

    // Scaler: count modalities whose full row-sum is exactly 0
    rsum[rs_m * BM + rs_r] = rs;
    __syncthreads();
    if (tid < BM) {
        int cnt = 0;
        #pragma unroll
        for (int m = 0; m < 4; m++)
            cnt += (rsum[m * BM + tid] == 0.0f) ? 1 : 0;
        scal[tid] = (cnt > 0) ? (float)(cnt + 1) : 1.0f;
    }
    __syncthreads();

    // Epilogue: softmax over modalities + weighted sum + rescale
    #pragma unroll
    for (int i = 0; i < 4; i++) {
        const int r  = ty * 4 + i;
        const int gb = b0 + r;
        const float sclr = scal[r];
        const int pair = i >> 1;
        const int half = i & 1;

        float xv[4][8];
        #pragma unroll
        for (int m = 0; m < 4; m++) {
            const float4 x0 = *(const float4*)(mods[m] + (size_t)gb * L_SZ + k0 + tx * 8);
            const float4 x1 = *(const float4*)(mods[m] + (size_t)gb * L_SZ + k0 + tx * 8 + 4);
            xv[m][0] = x0.x; xv[m][1] = x0.y; xv[m][2] = x0.z; xv[m][3] = x0.w;
            xv[m][4] = x1.x; xv[m][5] = x1.y; xv[m][6] = x1.z; xv[m][7] = x1.w;
        }

        float res[8];
        #pragma unroll
        for (int j = 0; j < 8; j++) {
            float sc[4];
            #pragma unroll
            for (int m = 0; m < 4; m++) {
                const u64 v = acc[m][j][pair];
                const unsigned h = half ? (unsigned)(v >> 32) : (unsigned)(v & 0xffffffffull);
                sc[m] = __uint_as_float(h);
            }
            const float mx = fmaxf(fmaxf(sc[0], sc[1]), fmaxf(sc[2], sc[3]));
            const float e0 = __expf(sc[0] - mx);
            const float e1 = __expf(sc[1] - mx);
            const float e2 = __expf(sc[2] - mx);
            const float e3 = __expf(sc[3] - mx);
            const float inv = 1.0f / (e0 + e1 + e2 + e3);
            res[j] = (e0 * xv[0][j] + e1 * xv[1][j] + e2 * xv[2][j] + e3 * xv[3][j])
                     * inv * sclr;
        }
        float4 o0 = make_float4(res[0], res[1], res[2], res[3]);
        float4 o1 = make_float4(res[4], res[5], res[6], res[7]);
        *(float4*)(out + (size_t)gb * L_SZ + k0 + tx * 8)     = o0;
        *(float4*)(out + (size_t)gb * L_SZ + k0 + tx * 8 + 4) = o1;
    }
}

extern "C" void kernel_launch(void* const* d_in, const int* in_sizes, int n_in,
                              void* d_out, int out_size)
{
    // Inputs: mod0, mod1, mod2, mod3 (each 16384*1024), W (1024*1024).
    // Identify W robustly by element count.
    const float* mods[4] = {nullptr, nullptr, nullptr, nullptr};
    const float* W = nullptr;
    int mi = 0;
    for (int i = 0; i < n_in; i++) {
        if (in_sizes[i] == L_SZ * L_SZ) {
            W = (const float*)d_in[i];
        } else if (mi < 4) {
            mods[mi++] = (const float*)d_in[i];
        }
    }
    if (!W) W = (const float*)d_in[n_in - 1];

    float* out = (float*)d_out;
    dim3 grid(L_SZ / BN, B_SZ / BM);   // (8, 256): k-tiles fastest -> A rows shared in L2
    fused_modal_attn_kernel<<<grid, NTHREADS>>>(mods[0], mods[1], mods[2], mods[3], W, out);
}

// round 3
// speedup vs baseline: 5.7246x; 5.7246x over previous
#include <cuda_runtime.h>
#include <cuda_fp16.h>
#include <cstdint>
#include <cstddef>

#define B_SZ 16384
#define L_SZ 1024
#define BM 64
#define BN 128
#define BK 32
#define NT 256
#define NCHUNK (L_SZ / BK)     // 32
#define STRIDE 40              // halves per smem row (80B: conflict-free ldmatrix)
#define OFF_ALO (4 * BM * STRIDE)        // 10240 halves
#define OFF_W   (2 * 4 * BM * STRIDE)    // 20480 halves
#define SMEM_BYTES ((OFF_W + BN * STRIDE) * 2)   // 51200 B

__device__ __forceinline__ uint32_t smem_u32(const void* p) {
    uint32_t a;
    asm("{ .reg .u64 t; cvta.to.shared.u64 t, %1; cvt.u32.u64 %0, t; }" : "=r"(a) : "l"(p));
    return a;
}

#define LDSM4(r0, r1, r2, r3, addr)                                        \
    asm volatile("ldmatrix.sync.aligned.m8n8.x4.shared.b16 {%0,%1,%2,%3}, [%4];" \
                 : "=r"(r0), "=r"(r1), "=r"(r2), "=r"(r3) : "r"(addr))

#define MMA16816(d, a0, a1, a2, a3, b0, b1)                                \
    asm volatile("mma.sync.aligned.m16n8k16.row.col.f32.f16.f16.f32 "      \
                 "{%0,%1,%2,%3}, {%4,%5,%6,%7}, {%8,%9}, {%0,%1,%2,%3};"   \
                 : "+f"((d)[0]), "+f"((d)[1]), "+f"((d)[2]), "+f"((d)[3])  \
                 : "r"(a0), "r"(a1), "r"(a2), "r"(a3), "r"(b0), "r"(b1))

__device__ __forceinline__ uint32_t h2u(__half2 h) {
    return *reinterpret_cast<uint32_t*>(&h);
}

__global__ __launch_bounds__(NT, 1)
void fused_modal_attn_hmma(const float* __restrict__ m0, const float* __restrict__ m1,
                           const float* __restrict__ m2, const float* __restrict__ m3,
                           const float* __restrict__ Wm, float* __restrict__ out)
{
    extern __shared__ __align__(16) __half sm[];
    __shared__ float rsum[4][NT];
    __shared__ float scal[BM];

    const float* mods[4] = {m0, m1, m2, m3};
    const int tid = threadIdx.x;
    const int wid = tid >> 5;
    const int lane = tid & 31;
    const int b0 = blockIdx.y * BM;
    const int k0 = blockIdx.x * BN;
    const int wm = wid & 1;        // row block: wm*32
    const int wn = wid >> 1;       // col block: wn*32

    // staging mapping
    const int s_row = tid >> 2;            // A row 0..63
    const int s_cg  = (tid & 3) * 8;       // A col group (8 floats)
    const int w_row = tid >> 1;            // W row 0..127
    const int w_cg  = (tid & 1) * 16;      // W col group (16 floats)

    // ldmatrix lane->address offsets (in halves)
    const int j = lane >> 3, r = lane & 7;
    const uint32_t laneA = (uint32_t)(((j & 1) * 8 + r) * STRIDE + (j >> 1) * 8);
    const uint32_t laneB = (uint32_t)(((j >> 1) * 8 + r) * STRIDE + (j & 1) * 8);
    const uint32_t smb = smem_u32(sm);

    float acc[4][2][4][4];
#pragma unroll
    for (int m = 0; m < 4; m++)
#pragma unroll
        for (int i = 0; i < 2; i++)
#pragma unroll
            for (int nt = 0; nt < 4; nt++)
#pragma unroll
                for (int c = 0; c < 4; c++) acc[m][i][nt][c] = 0.0f;

    float rs[4] = {0.f, 0.f, 0.f, 0.f};
    float4 aReg[4][2];
    float4 wReg[4];

    // prefetch chunk 0
#pragma unroll
    for (int m = 0; m < 4; m++) {
        const float* p = mods[m] + (size_t)(b0 + s_row) * L_SZ + s_cg;
        aReg[m][0] = *(const float4*)p;
        aReg[m][1] = *(const float4*)(p + 4);
    }
#pragma unroll
    for (int i = 0; i < 4; i++)
        wReg[i] = *(const float4*)(Wm + (size_t)(k0 + w_row) * L_SZ + w_cg + i * 4);

    for (int c = 0; c < NCHUNK; ++c) {
        __syncthreads();    // previous chunk's smem reads finished

        // ---- stage A (hi+lo fp16 split) ----
#pragma unroll
        for (int m = 0; m < 4; m++) {
            const float4 v0 = aReg[m][0], v1 = aReg[m][1];
            rs[m] += ((v0.x + v0.y) + (v0.z + v0.w)) + ((v1.x + v1.y) + (v1.z + v1.w));
            __half2 h0 = __floats2half2_rn(v0.x, v0.y);
            __half2 h1 = __floats2half2_rn(v0.z, v0.w);
            __half2 h2 = __floats2half2_rn(v1.x, v1.y);
            __half2 h3 = __floats2half2_rn(v1.z, v1.w);
            float2 f0 = __half22float2(h0), f1 = __half22float2(h1);
            float2 f2 = __half22float2(h2), f3 = __half22float2(h3);
            __half2 l0 = __floats2half2_rn(v0.x - f0.x, v0.y - f0.y);
            __half2 l1 = __floats2half2_rn(v0.z - f1.x, v0.w - f1.y);
            __half2 l2 = __floats2half2_rn(v1.x - f2.x, v1.y - f2.y);
            __half2 l3 = __floats2half2_rn(v1.z - f3.x, v1.w - f3.y);
            const uint32_t off = (uint32_t)(m * BM * STRIDE + s_row * STRIDE + s_cg);
            *reinterpret_cast<uint4*>((char*)sm + 2u * off) =
                make_uint4(h2u(h0), h2u(h1), h2u(h2), h2u(h3));
            *reinterpret_cast<uint4*>((char*)sm + 2u * (OFF_ALO + off)) =
                make_uint4(h2u(l0), h2u(l1), h2u(l2), h2u(l3));
        }
        // ---- stage W (hi only) ----
        {
            __half2 w0 = __floats2half2_rn(wReg[0].x, wReg[0].y);
            __half2 w1 = __floats2half2_rn(wReg[0].z, wReg[0].w);
            __half2 w2 = __floats2half2_rn(wReg[1].x, wReg[1].y);
            __half2 w3 = __floats2half2_rn(wReg[1].z, wReg[1].w);
            __half2 w4 = __floats2half2_rn(wReg[2].x, wReg[2].y);
            __half2 w5 = __floats2half2_rn(wReg[2].z, wReg[2].w);
            __half2 w6 = __floats2half2_rn(wReg[3].x, wReg[3].y);
            __half2 w7 = __floats2half2_rn(wReg[3].z, wReg[3].w);
            const uint32_t off = (uint32_t)(OFF_W + w_row * STRIDE + w_cg);
            *reinterpret_cast<uint4*>((char*)sm + 2u * off) =
                make_uint4(h2u(w0), h2u(w1), h2u(w2), h2u(w3));
            *reinterpret_cast<uint4*>((char*)sm + 2u * (off + 8)) =
                make_uint4(h2u(w4), h2u(w5), h2u(w6), h2u(w7));
        }
        __syncthreads();

        // ---- prefetch next chunk (hidden under MMA below) ----
        if (c + 1 < NCHUNK) {
            const int lb = (c + 1) * BK;
#pragma unroll
            for (int m = 0; m < 4; m++) {
                const float* p = mods[m] + (size_t)(b0 + s_row) * L_SZ + lb + s_cg;
                aReg[m][0] = *(const float4*)p;
                aReg[m][1] = *(const float4*)(p + 4);
            }
#pragma unroll
            for (int i = 0; i < 4; i++)
                wReg[i] = *(const float4*)(Wm + (size_t)(k0 + w_row) * L_SZ + lb + w_cg + i * 4);
        }

        // ---- MMA: scores += Ah*Wh + Al*Wh  (= A*Wh) ----
#pragma unroll
        for (int ks = 0; ks < 2; ks++) {
            uint32_t B[8];
            const uint32_t bBase =
                smb + 2u * (uint32_t)(OFF_W + (wn * 32) * STRIDE + ks * 16 + laneB);
            LDSM4(B[0], B[1], B[2], B[3], bBase);
            LDSM4(B[4], B[5], B[6], B[7], bBase + 2u * (16 * STRIDE));
#pragma unroll
            for (int m = 0; m < 4; m++) {
#pragma unroll
                for (int i = 0; i < 2; i++) {
                    const uint32_t aBase =
                        smb + 2u * (uint32_t)(m * BM * STRIDE + (wm * 32 + i * 16) * STRIDE
                                              + ks * 16 + laneA);
                    uint32_t A0, A1, A2, A3;
                    LDSM4(A0, A1, A2, A3, aBase);                       // hi
#pragma unroll
                    for (int nt = 0; nt < 4; nt++)
                        MMA16816(acc[m][i][nt], A0, A1, A2, A3, B[nt * 2], B[nt * 2 + 1]);
                    LDSM4(A0, A1, A2, A3, aBase + 2u * OFF_ALO);        // lo
#pragma unroll
                    for (int nt = 0; nt < 4; nt++)
                        MMA16816(acc[m][i][nt], A0, A1, A2, A3, B[nt * 2], B[nt * 2 + 1]);
                }
            }
        }
    }

    // ---- scaler from full-row sums ----
#pragma unroll
    for (int m = 0; m < 4; m++) rsum[m][tid] = rs[m];
    __syncthreads();
    if (tid < BM) {
        int cnt = 0;
#pragma unroll
        for (int m = 0; m < 4; m++) {
            const float s = (rsum[m][tid * 4 + 0] + rsum[m][tid * 4 + 1])
                          + (rsum[m][tid * 4 + 2] + rsum[m][tid * 4 + 3]);
            cnt += (s == 0.0f) ? 1 : 0;
        }
        scal[tid] = (cnt > 0) ? (float)(cnt + 1) : 1.0f;
    }
    __syncthreads();

    // ---- epilogue: softmax over modalities + weighted sum + rescale ----
    const int qr = lane >> 2;
    const int qc = (lane & 3) * 2;
#pragma unroll
    for (int i = 0; i < 2; i++) {
#pragma unroll
        for (int rp = 0; rp < 2; rp++) {
            const int row = wm * 32 + i * 16 + qr + rp * 8;
            const float sc_row = scal[row];
            const size_t g = (size_t)(b0 + row) * L_SZ + k0 + wn * 32;
#pragma unroll
            for (int nt = 0; nt < 4; nt++) {
                float2 x[4];
#pragma unroll
                for (int m = 0; m < 4; m++)
                    x[m] = *(const float2*)(mods[m] + g + nt * 8 + qc);
                float res[2];
#pragma unroll
                for (int cc = 0; cc < 2; cc++) {
                    const float s0 = acc[0][i][nt][rp * 2 + cc];
                    const float s1 = acc[1][i][nt][rp * 2 + cc];
                    const float s2 = acc[2][i][nt][rp * 2 + cc];
                    const float s3 = acc[3][i][nt][rp * 2 + cc];
                    const float mx = fmaxf(fmaxf(s0, s1), fmaxf(s2, s3));
                    const float e0 = __expf(s0 - mx);
                    const float e1 = __expf(s1 - mx);
                    const float e2 = __expf(s2 - mx);
                    const float e3 = __expf(s3 - mx);
                    const float inv = 1.0f / (e0 + e1 + e2 + e3);
                    const float x0 = cc ? x[0].y : x[0].x;
                    const float x1 = cc ? x[1].y : x[1].x;
                    const float x2 = cc ? x[2].y : x[2].x;
                    const float x3 = cc ? x[3].y : x[3].x;
                    res[cc] = (e0 * x0 + e1 * x1 + e2 * x2 + e3 * x3) * inv * sc_row;
                }
                *(float2*)(out + g + nt * 8 + qc) = make_float2(res[0], res[1]);
            }
        }
    }
}

extern "C" void kernel_launch(void* const* d_in, const int* in_sizes, int n_in,
                              void* d_out, int out_size)
{
    const float* mods[4] = {nullptr, nullptr, nullptr, nullptr};
    const float* W = nullptr;
    int mi = 0;
    for (int i = 0; i < n_in; i++) {
        if (in_sizes[i] == L_SZ * L_SZ) W = (const float*)d_in[i];
        else if (mi < 4) mods[mi++] = (const float*)d_in[i];
    }
    if (!W) W = (const float*)d_in[n_in - 1];

    static int configured = 0;
    cudaFuncSetAttribute(fused_modal_attn_hmma,
                         cudaFuncAttributeMaxDynamicSharedMemorySize, SMEM_BYTES);
    (void)configured;

    dim3 grid(L_SZ / BN, B_SZ / BM);   // (8, 256): k-tiles fastest -> A L2-coresident
    fused_modal_attn_hmma<<<grid, NT, SMEM_BYTES>>>(
        mods[0], mods[1], mods[2], mods[3], W, (float*)d_out);
}

// round 4
// speedup vs baseline: 7.6959x; 1.3444x over previous
#include <cuda_runtime.h>
#include <cuda_fp16.h>
#include <cstdint>
#include <cstddef>

#define B_SZ 16384
#define L_SZ 1024
#define BM 64
#define BN 128
#define BK 32
#define NT 256
#define NCHUNK (L_SZ / BK)     // 32
#define STRIDE 40              // halves per smem row (80B: conflict-free ldmatrix)
#define OFF_W   (4 * BM * STRIDE)                // 10240 halves
#define SMEM_BYTES ((OFF_W + BN * STRIDE) * 2)   // 30720 B

__device__ __forceinline__ uint32_t smem_u32(const void* p) {
    uint32_t a;
    asm("{ .reg .u64 t; cvta.to.shared.u64 t, %1; cvt.u32.u64 %0, t; }" : "=r"(a) : "l"(p));
    return a;
}

#define LDSM4(r0, r1, r2, r3, addr)                                        \
    asm volatile("ldmatrix.sync.aligned.m8n8.x4.shared.b16 {%0,%1,%2,%3}, [%4];" \
                 : "=r"(r0), "=r"(r1), "=r"(r2), "=r"(r3) : "r"(addr))

#define MMA16816(d, a0, a1, a2, a3, b0, b1)                                \
    asm volatile("mma.sync.aligned.m16n8k16.row.col.f32.f16.f16.f32 "      \
                 "{%0,%1,%2,%3}, {%4,%5,%6,%7}, {%8,%9}, {%0,%1,%2,%3};"   \
                 : "+f"((d)[0]), "+f"((d)[1]), "+f"((d)[2]), "+f"((d)[3])  \
                 : "r"(a0), "r"(a1), "r"(a2), "r"(a3), "r"(b0), "r"(b1))

__device__ __forceinline__ uint32_t h2u(__half2 h) {
    return *reinterpret_cast<uint32_t*>(&h);
}

__global__ __launch_bounds__(NT, 1)
void fused_modal_attn_hmma(const float* __restrict__ m0, const float* __restrict__ m1,
                           const float* __restrict__ m2, const float* __restrict__ m3,
                           const float* __restrict__ Wm, float* __restrict__ out)
{
    extern __shared__ __align__(16) __half sm[];
    __shared__ float rsum[4][NT];
    __shared__ float scal[BM];

    const float* mods[4] = {m0, m1, m2, m3};
    const int tid = threadIdx.x;
    const int wid = tid >> 5;
    const int lane = tid & 31;
    const int b0 = blockIdx.y * BM;
    const int k0 = blockIdx.x * BN;
    const int wm = wid & 3;        // row block: wm*16 (16 rows)
    const int wn = wid >> 2;       // col block: wn*64 (64 cols)

    // staging mapping
    const int s_row = tid >> 2;            // A row 0..63
    const int s_cg  = (tid & 3) * 8;       // A col group (8 floats)
    const int w_row = tid >> 1;            // W row 0..127
    const int w_cg  = (tid & 1) * 16;      // W col group (16 floats)

    // ldmatrix lane->address offsets (in halves)
    const int j = lane >> 3, r = lane & 7;
    const uint32_t laneA = (uint32_t)(((j & 1) * 8 + r) * STRIDE + (j >> 1) * 8);
    const uint32_t laneB = (uint32_t)(((j >> 1) * 8 + r) * STRIDE + (j & 1) * 8);
    const uint32_t smb = smem_u32(sm);

    float acc[4][8][4];
#pragma unroll
    for (int m = 0; m < 4; m++)
#pragma unroll
        for (int nt = 0; nt < 8; nt++)
#pragma unroll
            for (int c = 0; c < 4; c++) acc[m][nt][c] = 0.0f;

    float rs[4] = {0.f, 0.f, 0.f, 0.f};
    float4 aReg[4][2];
    float4 wReg[4];

    // prefetch chunk 0
#pragma unroll
    for (int m = 0; m < 4; m++) {
        const float* p = mods[m] + (size_t)(b0 + s_row) * L_SZ + s_cg;
        aReg[m][0] = *(const float4*)p;
        aReg[m][1] = *(const float4*)(p + 4);
    }
#pragma unroll
    for (int i = 0; i < 4; i++)
        wReg[i] = *(const float4*)(Wm + (size_t)(k0 + w_row) * L_SZ + w_cg + i * 4);

    for (int c = 0; c < NCHUNK; ++c) {
        __syncthreads();    // previous chunk's smem reads finished

        // ---- stage A (single fp16 hi) + rowsum ----
#pragma unroll
        for (int m = 0; m < 4; m++) {
            const float4 v0 = aReg[m][0], v1 = aReg[m][1];
            rs[m] += ((v0.x + v0.y) + (v0.z + v0.w)) + ((v1.x + v1.y) + (v1.z + v1.w));
            __half2 h0 = __floats2half2_rn(v0.x, v0.y);
            __half2 h1 = __floats2half2_rn(v0.z, v0.w);
            __half2 h2 = __floats2half2_rn(v1.x, v1.y);
            __half2 h3 = __floats2half2_rn(v1.z, v1.w);
            const uint32_t off = (uint32_t)(m * BM * STRIDE + s_row * STRIDE + s_cg);
            *reinterpret_cast<uint4*>((char*)sm + 2u * off) =
                make_uint4(h2u(h0), h2u(h1), h2u(h2), h2u(h3));
        }
        // ---- stage W ----
        {
            __half2 w0 = __floats2half2_rn(wReg[0].x, wReg[0].y);
            __half2 w1 = __floats2half2_rn(wReg[0].z, wReg[0].w);
            __half2 w2 = __floats2half2_rn(wReg[1].x, wReg[1].y);
            __half2 w3 = __floats2half2_rn(wReg[1].z, wReg[1].w);
            __half2 w4 = __floats2half2_rn(wReg[2].x, wReg[2].y);
            __half2 w5 = __floats2half2_rn(wReg[2].z, wReg[2].w);
            __half2 w6 = __floats2half2_rn(wReg[3].x, wReg[3].y);
            __half2 w7 = __floats2half2_rn(wReg[3].z, wReg[3].w);
            const uint32_t off = (uint32_t)(OFF_W + w_row * STRIDE + w_cg);
            *reinterpret_cast<uint4*>((char*)sm + 2u * off) =
                make_uint4(h2u(w0), h2u(w1), h2u(w2), h2u(w3));
            *reinterpret_cast<uint4*>((char*)sm + 2u * (off + 8)) =
                make_uint4(h2u(w4), h2u(w5), h2u(w6), h2u(w7));
        }
        __syncthreads();

        // ---- prefetch next chunk (hidden under MMA below) ----
        if (c + 1 < NCHUNK) {
            const int lb = (c + 1) * BK;
#pragma unroll
            for (int m = 0; m < 4; m++) {
                const float* p = mods[m] + (size_t)(b0 + s_row) * L_SZ + lb + s_cg;
                aReg[m][0] = *(const float4*)p;
                aReg[m][1] = *(const float4*)(p + 4);
            }
#pragma unroll
            for (int i = 0; i < 4; i++)
                wReg[i] = *(const float4*)(Wm + (size_t)(k0 + w_row) * L_SZ + lb + w_cg + i * 4);
        }

        // ---- MMA: scores += Ah*Wh ----
#pragma unroll
        for (int ks = 0; ks < 2; ks++) {
            uint32_t B[16];
            const uint32_t bBase =
                smb + 2u * (uint32_t)(OFF_W + (wn * 64) * STRIDE + ks * 16 + laneB);
#pragma unroll
            for (int t = 0; t < 4; t++)
                LDSM4(B[4 * t], B[4 * t + 1], B[4 * t + 2], B[4 * t + 3],
                      bBase + 2u * (uint32_t)(t * 16 * STRIDE));
#pragma unroll
            for (int m = 0; m < 4; m++) {
                const uint32_t aBase =
                    smb + 2u * (uint32_t)(m * BM * STRIDE + (wm * 16) * STRIDE
                                          + ks * 16 + laneA);
                uint32_t A0, A1, A2, A3;
                LDSM4(A0, A1, A2, A3, aBase);
#pragma unroll
                for (int nt = 0; nt < 8; nt++)
                    MMA16816(acc[m][nt], A0, A1, A2, A3, B[nt * 2], B[nt * 2 + 1]);
            }
        }
    }

    // ---- scaler from full-row sums ----
#pragma unroll
    for (int m = 0; m < 4; m++) rsum[m][tid] = rs[m];
    __syncthreads();
    if (tid < BM) {
        int cnt = 0;
#pragma unroll
        for (int m = 0; m < 4; m++) {
            const float s = (rsum[m][tid * 4 + 0] + rsum[m][tid * 4 + 1])
                          + (rsum[m][tid * 4 + 2] + rsum[m][tid * 4 + 3]);
            cnt += (s == 0.0f) ? 1 : 0;
        }
        scal[tid] = (cnt > 0) ? (float)(cnt + 1) : 1.0f;
    }
    __syncthreads();

    // ---- epilogue: softmax over modalities + weighted sum + rescale ----
    const int qr = lane >> 2;
    const int qc = (lane & 3) * 2;
#pragma unroll
    for (int rp = 0; rp < 2; rp++) {
        const int row = wm * 16 + qr + rp * 8;
        const float sc_row = scal[row];
        const size_t g = (size_t)(b0 + row) * L_SZ + k0 + wn * 64;
#pragma unroll
        for (int nt = 0; nt < 8; nt++) {
            float2 x[4];
#pragma unroll
            for (int m = 0; m < 4; m++)
                x[m] = *(const float2*)(mods[m] + g + nt * 8 + qc);
            float res[2];
#pragma unroll
            for (int cc = 0; cc < 2; cc++) {
                const float s0 = acc[0][nt][rp * 2 + cc];
                const float s1 = acc[1][nt][rp * 2 + cc];
                const float s2 = acc[2][nt][rp * 2 + cc];
                const float s3 = acc[3][nt][rp * 2 + cc];
                const float mx = fmaxf(fmaxf(s0, s1), fmaxf(s2, s3));
                const float e0 = __expf(s0 - mx);
                const float e1 = __expf(s1 - mx);
                const float e2 = __expf(s2 - mx);
                const float e3 = __expf(s3 - mx);
                const float inv = 1.0f / (e0 + e1 + e2 + e3);
                const float x0 = cc ? x[0].y : x[0].x;
                const float x1 = cc ? x[1].y : x[1].x;
                const float x2 = cc ? x[2].y : x[2].x;
                const float x3 = cc ? x[3].y : x[3].x;
                res[cc] = (e0 * x0 + e1 * x1 + e2 * x2 + e3 * x3) * inv * sc_row;
            }
            *(float2*)(out + g + nt * 8 + qc) = make_float2(res[0], res[1]);
        }
    }
}

extern "C" void kernel_launch(void* const* d_in, const int* in_sizes, int n_in,
                              void* d_out, int out_size)
{
    const float* mods[4] = {nullptr, nullptr, nullptr, nullptr};
    const float* W = nullptr;
    int mi = 0;
    for (int i = 0; i < n_in; i++) {
        if (in_sizes[i] == L_SZ * L_SZ) W = (const float*)d_in[i];
        else if (mi < 4) mods[mi++] = (const float*)d_in[i];
    }
    if (!W) W = (const float*)d_in[n_in - 1];

    cudaFuncSetAttribute(fused_modal_attn_hmma,
                         cudaFuncAttributeMaxDynamicSharedMemorySize, SMEM_BYTES);

    dim3 grid(L_SZ / BN, B_SZ / BM);   // (8, 256): k-tiles fastest -> A L2-coresident
    fused_modal_attn_hmma<<<grid, NT, SMEM_BYTES>>>(
        mods[0], mods[1], mods[2], mods[3], W, (float*)d_out);
}

// round 5
// speedup vs baseline: 7.8364x; 1.0183x over previous
#include <cuda_runtime.h>
#include <cuda_fp16.h>
#include <cstdint>
#include <cstddef>

#define B_SZ 16384
#define L_SZ 1024
#define BM 64
#define BN 128
#define BK 32
#define NT 256
#define NCHUNK (L_SZ / BK)     // 32
#define STRIDE 40              // halves per smem row (80B: conflict-free ldmatrix)
#define A_HALVES (4 * BM * STRIDE)           // 10240 halves per buffer (A part)
#define W_OFFH   A_HALVES
#define BUF_HALVES (A_HALVES + BN * STRIDE)  // 15360 halves = 30720 B
#define SMEM_BYTES (2 * BUF_HALVES * 2)      // 61440 B (double buffered)

// Static scratch (sanctioned workaround: __device__ globals, no runtime alloc)
__device__ __half g_A[4][B_SZ][L_SZ];   // 128 MB fp16 pre-converted modalities
__device__ __half g_W[L_SZ][L_SZ];      // 2 MB fp16 pre-converted W
__device__ float  g_scal[B_SZ];         // per-row rescale factor

__device__ __forceinline__ uint32_t smem_u32(const void* p) {
    uint32_t a;
    asm("{ .reg .u64 t; cvta.to.shared.u64 t, %1; cvt.u32.u64 %0, t; }" : "=r"(a) : "l"(p));
    return a;
}

#define LDSM4(r0, r1, r2, r3, addr)                                        \
    asm volatile("ldmatrix.sync.aligned.m8n8.x4.shared.b16 {%0,%1,%2,%3}, [%4];" \
                 : "=r"(r0), "=r"(r1), "=r"(r2), "=r"(r3) : "r"(addr))

#define MMA16816(d, a0, a1, a2, a3, b0, b1)                                \
    asm volatile("mma.sync.aligned.m16n8k16.row.col.f32.f16.f16.f32 "      \
                 "{%0,%1,%2,%3}, {%4,%5,%6,%7}, {%8,%9}, {%0,%1,%2,%3};"   \
                 : "+f"((d)[0]), "+f"((d)[1]), "+f"((d)[2]), "+f"((d)[3])  \
                 : "r"(a0), "r"(a1), "r"(a2), "r"(a3), "r"(b0), "r"(b1))

#define CP16(dst, src) \
    asm volatile("cp.async.cg.shared.global [%0], [%1], 16;" :: "r"(dst), "l"(src))
#define CP_COMMIT() asm volatile("cp.async.commit_group;" ::: "memory")
#define CP_WAIT(n)  asm volatile("cp.async.wait_group %0;" :: "n"(n) : "memory")

__device__ __forceinline__ uint32_t h2u(__half2 h) {
    return *reinterpret_cast<uint32_t*>(&h);
}

// ---------------------------------------------------------------------------
// Prep: fp32 -> fp16 for the 4 modalities + W; row-sum scaler.
// grid = B_SZ + L_SZ blocks, 128 threads. Block b < B_SZ handles batch row b
// (all 4 mods); block B_SZ + r converts W row r.
// ---------------------------------------------------------------------------
__global__ __launch_bounds__(128, 8)
void prep_kernel(const float* __restrict__ m0, const float* __restrict__ m1,
                 const float* __restrict__ m2, const float* __restrict__ m3,
                 const float* __restrict__ Wm)
{
    const int t = threadIdx.x;
    const int bid = blockIdx.x;
    if (bid < B_SZ) {
        const float* mods[4] = {m0, m1, m2, m3};
        __shared__ float red[4][4];
#pragma unroll
        for (int m = 0; m < 4; m++) {
            const float* p = mods[m] + (size_t)bid * L_SZ + t * 8;
            const float4 v0 = *(const float4*)p;
            const float4 v1 = *(const float4*)(p + 4);
            float s = ((v0.x + v0.y) + (v0.z + v0.w)) + ((v1.x + v1.y) + (v1.z + v1.w));
            __half2 h0 = __floats2half2_rn(v0.x, v0.y);
            __half2 h1 = __floats2half2_rn(v0.z, v0.w);
            __half2 h2 = __floats2half2_rn(v1.x, v1.y);
            __half2 h3 = __floats2half2_rn(v1.z, v1.w);
            *reinterpret_cast<uint4*>(&g_A[m][bid][t * 8]) =
                make_uint4(h2u(h0), h2u(h1), h2u(h2), h2u(h3));
#pragma unroll
            for (int off = 16; off > 0; off >>= 1)
                s += __shfl_xor_sync(0xffffffffu, s, off);
            if ((t & 31) == 0) red[m][t >> 5] = s;
        }
        __syncthreads();
        if (t == 0) {
            int cnt = 0;
#pragma unroll
            for (int m = 0; m < 4; m++) {
                const float s = (red[m][0] + red[m][1]) + (red[m][2] + red[m][3]);
                cnt += (s == 0.0f) ? 1 : 0;
            }
            g_scal[bid] = (cnt > 0) ? (float)(cnt + 1) : 1.0f;
        }
    } else {
        const int row = bid - B_SZ;
        const float* p = Wm + (size_t)row * L_SZ + t * 8;
        const float4 v0 = *(const float4*)p;
        const float4 v1 = *(const float4*)(p + 4);
        __half2 h0 = __floats2half2_rn(v0.x, v0.y);
        __half2 h1 = __floats2half2_rn(v0.z, v0.w);
        __half2 h2 = __floats2half2_rn(v1.x, v1.y);
        __half2 h3 = __floats2half2_rn(v1.z, v1.w);
        *reinterpret_cast<uint4*>(&g_W[row][t * 8]) =
            make_uint4(h2u(h0), h2u(h1), h2u(h2), h2u(h3));
    }
}

// ---------------------------------------------------------------------------
// Main: fp16 HMMA mainloop fed by cp.async, double-buffered.
// ---------------------------------------------------------------------------
__global__ __launch_bounds__(NT, 1)
void fused_modal_attn_hmma(const float* __restrict__ m0, const float* __restrict__ m1,
                           const float* __restrict__ m2, const float* __restrict__ m3,
                           float* __restrict__ out)
{
    extern __shared__ __align__(16) __half sm[];

    const float* mods[4] = {m0, m1, m2, m3};
    const int tid = threadIdx.x;
    const int wid = tid >> 5;
    const int lane = tid & 31;
    const int b0 = blockIdx.y * BM;
    const int k0 = blockIdx.x * BN;
    const int wm = wid & 3;        // row block: wm*16
    const int wn = wid >> 2;       // col block: wn*64

    // cp.async mappings
    const int a_mrow = tid >> 2;          // 0..63 within this i-step group of 64
    const int a_seg  = (tid & 3);         // 16B segment within 64B row-chunk
    // ldmatrix lane offsets (halves)
    const int j = lane >> 3, r = lane & 7;
    const uint32_t laneA = (uint32_t)(((j & 1) * 8 + r) * STRIDE + (j >> 1) * 8);
    const uint32_t laneB = (uint32_t)(((j >> 1) * 8 + r) * STRIDE + (j & 1) * 8);
    const uint32_t smb = smem_u32(sm);

    float acc[4][8][4];
#pragma unroll
    for (int m = 0; m < 4; m++)
#pragma unroll
        for (int nt = 0; nt < 8; nt++)
#pragma unroll
            for (int c = 0; c < 4; c++) acc[m][nt][c] = 0.0f;

    // issue cp.async for chunk c into buffer s
    auto issue = [&](int c, int s) {
        const int lb = c * BK;
        const uint32_t bufB = smb + (uint32_t)(s * BUF_HALVES) * 2u;
#pragma unroll
        for (int i = 0; i < 4; i++) {    // A: 4 mods x 64 rows x 64B
            const int mrow = a_mrow + i * 64;          // 0..255
            const int mod = mrow >> 6, row = mrow & 63;
            const uint32_t dst = bufB + 2u * (uint32_t)(mrow * STRIDE + a_seg * 8);
            CP16(dst, &g_A[mod][b0 + row][lb + a_seg * 8]);
        }
#pragma unroll
        for (int i = 0; i < 2; i++) {    // W: 128 rows x 64B
            const int idx = tid + i * NT;
            const int row = idx >> 2, seg = idx & 3;
            const uint32_t dst = bufB + 2u * (uint32_t)(W_OFFH + row * STRIDE + seg * 8);
            CP16(dst, &g_W[k0 + row][lb + seg * 8]);
        }
        CP_COMMIT();
    };

    issue(0, 0);

    for (int c = 0; c < NCHUNK; ++c) {
        if (c + 1 < NCHUNK) { issue(c + 1, (c + 1) & 1); CP_WAIT(1); }
        else                { CP_WAIT(0); }
        __syncthreads();

        const uint32_t bufB = smb + (uint32_t)((c & 1) * BUF_HALVES) * 2u;
#pragma unroll
        for (int ks = 0; ks < 2; ks++) {
            uint32_t B[16];
            const uint32_t bBase =
                bufB + 2u * (uint32_t)(W_OFFH + (wn * 64) * STRIDE + ks * 16 + laneB);
#pragma unroll
            for (int t = 0; t < 4; t++)
                LDSM4(B[4 * t], B[4 * t + 1], B[4 * t + 2], B[4 * t + 3],
                      bBase + 2u * (uint32_t)(t * 16 * STRIDE));
#pragma unroll
            for (int m = 0; m < 4; m++) {
                const uint32_t aBase =
                    bufB + 2u * (uint32_t)(m * BM * STRIDE + (wm * 16) * STRIDE
                                           + ks * 16 + laneA);
                uint32_t A0, A1, A2, A3;
                LDSM4(A0, A1, A2, A3, aBase);
#pragma unroll
                for (int nt = 0; nt < 8; nt++)
                    MMA16816(acc[m][nt], A0, A1, A2, A3, B[nt * 2], B[nt * 2 + 1]);
            }
        }
        __syncthreads();   // MMA(c) done CTA-wide before buffer (c&1) is refilled
    }

    // ---- epilogue: softmax over modalities + weighted sum + rescale ----
    const int qr = lane >> 2;
    const int qc = (lane & 3) * 2;
#pragma unroll
    for (int rp = 0; rp < 2; rp++) {
        const int row = wm * 16 + qr + rp * 8;
        const float sc_row = g_scal[b0 + row];
        const size_t g = (size_t)(b0 + row) * L_SZ + k0 + wn * 64;
#pragma unroll
        for (int nt = 0; nt < 8; nt++) {
            float2 x[4];
#pragma unroll
            for (int m = 0; m < 4; m++)
                x[m] = *(const float2*)(mods[m] + g + nt * 8 + qc);
            float res[2];
#pragma unroll
            for (int cc = 0; cc < 2; cc++) {
                const float s0 = acc[0][nt][rp * 2 + cc];
                const float s1 = acc[1][nt][rp * 2 + cc];
                const float s2 = acc[2][nt][rp * 2 + cc];
                const float s3 = acc[3][nt][rp * 2 + cc];
                const float mx = fmaxf(fmaxf(s0, s1), fmaxf(s2, s3));
                const float e0 = __expf(s0 - mx);
                const float e1 = __expf(s1 - mx);
                const float e2 = __expf(s2 - mx);
                const float e3 = __expf(s3 - mx);
                const float inv = 1.0f / (e0 + e1 + e2 + e3);
                const float x0 = cc ? x[0].y : x[0].x;
                const float x1 = cc ? x[1].y : x[1].x;
                const float x2 = cc ? x[2].y : x[2].x;
                const float x3 = cc ? x[3].y : x[3].x;
                res[cc] = (e0 * x0 + e1 * x1 + e2 * x2 + e3 * x3) * inv * sc_row;
            }
            *(float2*)(out + g + nt * 8 + qc) = make_float2(res[0], res[1]);
        }
    }
}

extern "C" void kernel_launch(void* const* d_in, const int* in_sizes, int n_in,
                              void* d_out, int out_size)
{
    const float* mods[4] = {nullptr, nullptr, nullptr, nullptr};
    const float* W = nullptr;
    int mi = 0;
    for (int i = 0; i < n_in; i++) {
        if (in_sizes[i] == L_SZ * L_SZ) W = (const float*)d_in[i];
        else if (mi < 4) mods[mi++] = (const float*)d_in[i];
    }
    if (!W) W = (const float*)d_in[n_in - 1];

    cudaFuncSetAttribute(fused_modal_attn_hmma,
                         cudaFuncAttributeMaxDynamicSharedMemorySize, SMEM_BYTES);

    prep_kernel<<<B_SZ + L_SZ, 128>>>(mods[0], mods[1], mods[2], mods[3], W);

    dim3 grid(L_SZ / BN, B_SZ / BM);   // (8, 256): k-tiles fastest -> A L2-coresident
    fused_modal_attn_hmma<<<grid, NT, SMEM_BYTES>>>(
        mods[0], mods[1], mods[2], mods[3], (float*)d_out);
}

// round 6
// speedup vs baseline: 9.2272x; 1.1775x over previous
#include <cuda_runtime.h>
#include <cuda_fp16.h>
#include <cstdint>
#include <cstddef>

#define B_SZ 16384
#define L_SZ 1024
#define BM 64
#define BN 128
#define BK 64
#define NT 256
#define NCHUNK (L_SZ / BK)     // 16
#define NSTAGE 3
#define STRIDE 72              // halves per smem row (144B: conflict-free ldmatrix)
#define A_HALVES (4 * BM * STRIDE)           // 18432 halves per stage (A part)
#define W_OFFH   A_HALVES
#define STG_HALVES (A_HALVES + BN * STRIDE)  // 27648 halves = 55296 B
#define SMEM_BYTES (NSTAGE * STG_HALVES * 2) // 165888 B

// Static scratch (sanctioned: __device__ globals, no runtime alloc)
__device__ __half g_A[4][B_SZ][L_SZ];   // 128 MB fp16 pre-converted modalities
__device__ __half g_W[L_SZ][L_SZ];      // 2 MB fp16 pre-converted W
__device__ float  g_scal[B_SZ];         // per-row rescale factor

__device__ __forceinline__ uint32_t smem_u32(const void* p) {
    uint32_t a;
    asm("{ .reg .u64 t; cvta.to.shared.u64 t, %1; cvt.u32.u64 %0, t; }" : "=r"(a) : "l"(p));
    return a;
}

#define LDSM4(r0, r1, r2, r3, addr)                                        \
    asm volatile("ldmatrix.sync.aligned.m8n8.x4.shared.b16 {%0,%1,%2,%3}, [%4];" \
                 : "=r"(r0), "=r"(r1), "=r"(r2), "=r"(r3) : "r"(addr))

#define MMA16816(d, a0, a1, a2, a3, b0, b1)                                \
    asm volatile("mma.sync.aligned.m16n8k16.row.col.f32.f16.f16.f32 "      \
                 "{%0,%1,%2,%3}, {%4,%5,%6,%7}, {%8,%9}, {%0,%1,%2,%3};"   \
                 : "+f"((d)[0]), "+f"((d)[1]), "+f"((d)[2]), "+f"((d)[3])  \
                 : "r"(a0), "r"(a1), "r"(a2), "r"(a3), "r"(b0), "r"(b1))

#define CP16(dst, src) \
    asm volatile("cp.async.cg.shared.global [%0], [%1], 16;" :: "r"(dst), "l"(src))
#define CP_COMMIT() asm volatile("cp.async.commit_group;" ::: "memory")
#define CP_WAIT(n)  asm volatile("cp.async.wait_group %0;" :: "n"(n) : "memory")

__device__ __forceinline__ uint32_t h2u(__half2 h) {
    return *reinterpret_cast<uint32_t*>(&h);
}

// ---------------------------------------------------------------------------
// Prep: fp32 -> fp16 for the 4 modalities + W; row-sum scaler.
// ---------------------------------------------------------------------------
__global__ __launch_bounds__(128, 8)
void prep_kernel(const float* __restrict__ m0, const float* __restrict__ m1,
                 const float* __restrict__ m2, const float* __restrict__ m3,
                 const float* __restrict__ Wm)
{
    const int t = threadIdx.x;
    const int bid = blockIdx.x;
    if (bid < B_SZ) {
        const float* mods[4] = {m0, m1, m2, m3};
        __shared__ float red[4][4];
#pragma unroll
        for (int m = 0; m < 4; m++) {
            const float* p = mods[m] + (size_t)bid * L_SZ + t * 8;
            const float4 v0 = *(const float4*)p;
            const float4 v1 = *(const float4*)(p + 4);
            float s = ((v0.x + v0.y) + (v0.z + v0.w)) + ((v1.x + v1.y) + (v1.z + v1.w));
            __half2 h0 = __floats2half2_rn(v0.x, v0.y);
            __half2 h1 = __floats2half2_rn(v0.z, v0.w);
            __half2 h2 = __floats2half2_rn(v1.x, v1.y);
            __half2 h3 = __floats2half2_rn(v1.z, v1.w);
            *reinterpret_cast<uint4*>(&g_A[m][bid][t * 8]) =
                make_uint4(h2u(h0), h2u(h1), h2u(h2), h2u(h3));
#pragma unroll
            for (int off = 16; off > 0; off >>= 1)
                s += __shfl_xor_sync(0xffffffffu, s, off);
            if ((t & 31) == 0) red[m][t >> 5] = s;
        }
        __syncthreads();
        if (t == 0) {
            int cnt = 0;
#pragma unroll
            for (int m = 0; m < 4; m++) {
                const float s = (red[m][0] + red[m][1]) + (red[m][2] + red[m][3]);
                cnt += (s == 0.0f) ? 1 : 0;
            }
            g_scal[bid] = (cnt > 0) ? (float)(cnt + 1) : 1.0f;
        }
    } else {
        const int row = bid - B_SZ;
        const float* p = Wm + (size_t)row * L_SZ + t * 8;
        const float4 v0 = *(const float4*)p;
        const float4 v1 = *(const float4*)(p + 4);
        __half2 h0 = __floats2half2_rn(v0.x, v0.y);
        __half2 h1 = __floats2half2_rn(v0.z, v0.w);
        __half2 h2 = __floats2half2_rn(v1.x, v1.y);
        __half2 h3 = __floats2half2_rn(v1.z, v1.w);
        *reinterpret_cast<uint4*>(&g_W[row][t * 8]) =
            make_uint4(h2u(h0), h2u(h1), h2u(h2), h2u(h3));
    }
}

// ---------------------------------------------------------------------------
// Main: fp16 HMMA mainloop, 3-stage cp.async ring, one barrier per chunk.
// ---------------------------------------------------------------------------
__global__ __launch_bounds__(NT, 1)
void fused_modal_attn_hmma(const float* __restrict__ m0, const float* __restrict__ m1,
                           const float* __restrict__ m2, const float* __restrict__ m3,
                           float* __restrict__ out)
{
    extern __shared__ __align__(16) __half sm[];

    const float* mods[4] = {m0, m1, m2, m3};
    const int tid = threadIdx.x;
    const int wid = tid >> 5;
    const int lane = tid & 31;
    const int b0 = blockIdx.y * BM;
    const int k0 = blockIdx.x * BN;
    const int wm = wid & 3;        // row block: wm*16
    const int wn = wid >> 2;       // col block: wn*64

    // ldmatrix lane offsets (halves)
    const int j = lane >> 3, r = lane & 7;
    const uint32_t laneA = (uint32_t)(((j & 1) * 8 + r) * STRIDE + (j >> 1) * 8);
    const uint32_t laneB = (uint32_t)(((j >> 1) * 8 + r) * STRIDE + (j & 1) * 8);
    const uint32_t smb = smem_u32(sm);

    float acc[4][8][4];
#pragma unroll
    for (int m = 0; m < 4; m++)
#pragma unroll
        for (int nt = 0; nt < 8; nt++)
#pragma unroll
            for (int c = 0; c < 4; c++) acc[m][nt][c] = 0.0f;

    // issue cp.async for chunk c into stage s (A: 256 rows x 128B, W: 128 rows x 128B)
    auto issue = [&](int c, int s) {
        const int lb = c * BK;
        const uint32_t buf = smb + (uint32_t)(s * STG_HALVES) * 2u;
#pragma unroll
        for (int i = 0; i < 8; i++) {       // A: 2048 (row,seg) pairs
            const int idx = tid + i * NT;
            const int mrow = idx >> 3, seg = idx & 7;    // mrow 0..255
            const int mod = mrow >> 6, row = mrow & 63;
            const uint32_t dst = buf + 2u * (uint32_t)(mrow * STRIDE + seg * 8);
            CP16(dst, &g_A[mod][b0 + row][lb + seg * 8]);
        }
#pragma unroll
        for (int i = 0; i < 4; i++) {       // W: 1024 (row,seg) pairs
            const int idx = tid + i * NT;
            const int row = idx >> 3, seg = idx & 7;
            const uint32_t dst = buf + 2u * (uint32_t)(W_OFFH + row * STRIDE + seg * 8);
            CP16(dst, &g_W[k0 + row][lb + seg * 8]);
        }
        CP_COMMIT();
    };

    issue(0, 0);
    issue(1, 1);

    for (int c = 0; c < NCHUNK; ++c) {
        CP_WAIT(1);          // group for chunk c complete
        __syncthreads();     // all warps done with chunk c-1 -> stage (c+2)%3 free
        if (c + 2 < NCHUNK) issue(c + 2, (c + 2) % NSTAGE);
        else CP_COMMIT();    // keep group-count semantics exact in the tail

        const uint32_t buf = smb + (uint32_t)((c % NSTAGE) * STG_HALVES) * 2u;
#pragma unroll
        for (int ks = 0; ks < 4; ks++) {
            uint32_t B[16];
            const uint32_t bBase =
                buf + 2u * (uint32_t)(W_OFFH + (wn * 64) * STRIDE + ks * 16 + laneB);
#pragma unroll
            for (int t = 0; t < 4; t++)
                LDSM4(B[4 * t], B[4 * t + 1], B[4 * t + 2], B[4 * t + 3],
                      bBase + 2u * (uint32_t)(t * 16 * STRIDE));
#pragma unroll
            for (int m = 0; m < 4; m++) {
                const uint32_t aBase =
                    buf + 2u * (uint32_t)(m * BM * STRIDE + (wm * 16) * STRIDE
                                          + ks * 16 + laneA);
                uint32_t A0, A1, A2, A3;
                LDSM4(A0, A1, A2, A3, aBase);
#pragma unroll
                for (int nt = 0; nt < 8; nt++)
                    MMA16816(acc[m][nt], A0, A1, A2, A3, B[nt * 2], B[nt * 2 + 1]);
            }
        }
    }

    // ---- epilogue: softmax over modalities + weighted sum + rescale ----
    const int qr = lane >> 2;
    const int qc = (lane & 3) * 2;
#pragma unroll
    for (int rp = 0; rp < 2; rp++) {
        const int row = wm * 16 + qr + rp * 8;
        const float sc_row = g_scal[b0 + row];
        const size_t g = (size_t)(b0 + row) * L_SZ + k0 + wn * 64;
#pragma unroll
        for (int nt = 0; nt < 8; nt++) {
            float2 x[4];
#pragma unroll
            for (int m = 0; m < 4; m++)
                x[m] = *(const float2*)(mods[m] + g + nt * 8 + qc);
            float res[2];
#pragma unroll
            for (int cc = 0; cc < 2; cc++) {
                const float s0 = acc[0][nt][rp * 2 + cc];
                const float s1 = acc[1][nt][rp * 2 + cc];
                const float s2 = acc[2][nt][rp * 2 + cc];
                const float s3 = acc[3][nt][rp * 2 + cc];
                const float mx = fmaxf(fmaxf(s0, s1), fmaxf(s2, s3));
                const float e0 = __expf(s0 - mx);
                const float e1 = __expf(s1 - mx);
                const float e2 = __expf(s2 - mx);
                const float e3 = __expf(s3 - mx);
                const float inv = 1.0f / (e0 + e1 + e2 + e3);
                const float x0 = cc ? x[0].y : x[0].x;
                const float x1 = cc ? x[1].y : x[1].x;
                const float x2 = cc ? x[2].y : x[2].x;
                const float x3 = cc ? x[3].y : x[3].x;
                res[cc] = (e0 * x0 + e1 * x1 + e2 * x2 + e3 * x3) * inv * sc_row;
            }
            *(float2*)(out + g + nt * 8 + qc) = make_float2(res[0], res[1]);
        }
    }
}

extern "C" void kernel_launch(void* const* d_in, const int* in_sizes, int n_in,
                              void* d_out, int out_size)
{
    const float* mods[4] = {nullptr, nullptr, nullptr, nullptr};
    const float* W = nullptr;
    int mi = 0;
    for (int i = 0; i < n_in; i++) {
        if (in_sizes[i] == L_SZ * L_SZ) W = (const float*)d_in[i];
        else if (mi < 4) mods[mi++] = (const float*)d_in[i];
    }
    if (!W) W = (const float*)d_in[n_in - 1];

    cudaFuncSetAttribute(fused_modal_attn_hmma,
                         cudaFuncAttributeMaxDynamicSharedMemorySize, SMEM_BYTES);

    prep_kernel<<<B_SZ + L_SZ, 128>>>(mods[0], mods[1], mods[2], mods[3], W);

    dim3 grid(L_SZ / BN, B_SZ / BM);   // (8, 256): k-tiles fastest -> A L2-coresident
    fused_modal_attn_hmma<<<grid, NT, SMEM_BYTES>>>(
        mods[0], mods[1], mods[2], mods[3], (float*)d_out);
}

// round 7
// speedup vs baseline: 9.8411x; 1.0665x over previous
#include <cuda_runtime.h>
#include <cuda_fp16.h>
#include <cstdint>
#include <cstddef>

#define B_SZ 16384
#define L_SZ 1024
#define BM 64
#define BN 128
#define BK 64
#define NT 512
#define NCHUNK (L_SZ / BK)     // 16
#define NSTAGE 3
#define STRIDE 72              // halves per smem row (144B: conflict-free ldmatrix)
#define A_HALVES (4 * BM * STRIDE)           // 18432 halves per stage (A part)
#define W_OFFH   A_HALVES
#define STG_HALVES (A_HALVES + BN * STRIDE)  // 27648 halves = 55296 B
#define SMEM_BYTES (NSTAGE * STG_HALVES * 2) // 165888 B

// Static scratch (sanctioned: __device__ globals, no runtime alloc)
__device__ __half g_A[4][B_SZ][L_SZ];   // 128 MB fp16 pre-converted modalities
__device__ __half g_W[L_SZ][L_SZ];      // 2 MB fp16 pre-converted W
__device__ float  g_scal[B_SZ];         // per-row rescale factor

__device__ __forceinline__ uint32_t smem_u32(const void* p) {
    uint32_t a;
    asm("{ .reg .u64 t; cvta.to.shared.u64 t, %1; cvt.u32.u64 %0, t; }" : "=r"(a) : "l"(p));
    return a;
}

#define LDSM4(r0, r1, r2, r3, addr)                                        \
    asm volatile("ldmatrix.sync.aligned.m8n8.x4.shared.b16 {%0,%1,%2,%3}, [%4];" \
                 : "=r"(r0), "=r"(r1), "=r"(r2), "=r"(r3) : "r"(addr))

#define MMA16816(d, a0, a1, a2, a3, b0, b1)                                \
    asm volatile("mma.sync.aligned.m16n8k16.row.col.f32.f16.f16.f32 "      \
                 "{%0,%1,%2,%3}, {%4,%5,%6,%7}, {%8,%9}, {%0,%1,%2,%3};"   \
                 : "+f"((d)[0]), "+f"((d)[1]), "+f"((d)[2]), "+f"((d)[3])  \
                 : "r"(a0), "r"(a1), "r"(a2), "r"(a3), "r"(b0), "r"(b1))

#define CP16(dst, src) \
    asm volatile("cp.async.cg.shared.global [%0], [%1], 16;" :: "r"(dst), "l"(src))
#define CP_COMMIT() asm volatile("cp.async.commit_group;" ::: "memory")
#define CP_WAIT(n)  asm volatile("cp.async.wait_group %0;" :: "n"(n) : "memory")

__device__ __forceinline__ uint32_t h2u(__half2 h) {
    return *reinterpret_cast<uint32_t*>(&h);
}

// ---------------------------------------------------------------------------
// Prep: fp32 -> fp16 for the 4 modalities + W; row-sum scaler.
// ---------------------------------------------------------------------------
__global__ __launch_bounds__(128, 8)
void prep_kernel(const float* __restrict__ m0, const float* __restrict__ m1,
                 const float* __restrict__ m2, const float* __restrict__ m3,
                 const float* __restrict__ Wm)
{
    const int t = threadIdx.x;
    const int bid = blockIdx.x;
    if (bid < B_SZ) {
        const float* mods[4] = {m0, m1, m2, m3};
        __shared__ float red[4][4];
#pragma unroll
        for (int m = 0; m < 4; m++) {
            const float* p = mods[m] + (size_t)bid * L_SZ + t * 8;
            const float4 v0 = *(const float4*)p;
            const float4 v1 = *(const float4*)(p + 4);
            float s = ((v0.x + v0.y) + (v0.z + v0.w)) + ((v1.x + v1.y) + (v1.z + v1.w));
            __half2 h0 = __floats2half2_rn(v0.x, v0.y);
            __half2 h1 = __floats2half2_rn(v0.z, v0.w);
            __half2 h2 = __floats2half2_rn(v1.x, v1.y);
            __half2 h3 = __floats2half2_rn(v1.z, v1.w);
            *reinterpret_cast<uint4*>(&g_A[m][bid][t * 8]) =
                make_uint4(h2u(h0), h2u(h1), h2u(h2), h2u(h3));
#pragma unroll
            for (int off = 16; off > 0; off >>= 1)
                s += __shfl_xor_sync(0xffffffffu, s, off);
            if ((t & 31) == 0) red[m][t >> 5] = s;
        }
        __syncthreads();
        if (t == 0) {
            int cnt = 0;
#pragma unroll
            for (int m = 0; m < 4; m++) {
                const float s = (red[m][0] + red[m][1]) + (red[m][2] + red[m][3]);
                cnt += (s == 0.0f) ? 1 : 0;
            }
            g_scal[bid] = (cnt > 0) ? (float)(cnt + 1) : 1.0f;
        }
    } else {
        const int row = bid - B_SZ;
        const float* p = Wm + (size_t)row * L_SZ + t * 8;
        const float4 v0 = *(const float4*)p;
        const float4 v1 = *(const float4*)(p + 4);
        __half2 h0 = __floats2half2_rn(v0.x, v0.y);
        __half2 h1 = __floats2half2_rn(v0.z, v0.w);
        __half2 h2 = __floats2half2_rn(v1.x, v1.y);
        __half2 h3 = __floats2half2_rn(v1.z, v1.w);
        *reinterpret_cast<uint4*>(&g_W[row][t * 8]) =
            make_uint4(h2u(h0), h2u(h1), h2u(h2), h2u(h3));
    }
}

// ---------------------------------------------------------------------------
// Main: fp16 HMMA mainloop, 512 threads (16 warps), 3-stage cp.async ring.
// Warp tile 16x32: wm = wid&3 (rows), wn = wid>>2 (cols).
// ---------------------------------------------------------------------------
__global__ __launch_bounds__(NT, 1)
void fused_modal_attn_hmma(const float* __restrict__ m0, const float* __restrict__ m1,
                           const float* __restrict__ m2, const float* __restrict__ m3,
                           float* __restrict__ out)
{
    extern __shared__ __align__(16) __half sm[];

    const float* mods[4] = {m0, m1, m2, m3};
    const int tid = threadIdx.x;
    const int wid = tid >> 5;
    const int lane = tid & 31;
    const int b0 = blockIdx.y * BM;
    const int k0 = blockIdx.x * BN;
    const int wm = wid & 3;        // row block: wm*16
    const int wn = wid >> 2;       // col block: wn*32

    // ldmatrix lane offsets (halves)
    const int j = lane >> 3, r = lane & 7;
    const uint32_t laneA = (uint32_t)(((j & 1) * 8 + r) * STRIDE + (j >> 1) * 8);
    const uint32_t laneB = (uint32_t)(((j >> 1) * 8 + r) * STRIDE + (j & 1) * 8);
    const uint32_t smb = smem_u32(sm);

    float acc[4][4][4];   // [mod][n8-tile][frag]
#pragma unroll
    for (int m = 0; m < 4; m++)
#pragma unroll
        for (int nt = 0; nt < 4; nt++)
#pragma unroll
            for (int c = 0; c < 4; c++) acc[m][nt][c] = 0.0f;

    // issue cp.async for chunk c into stage s (A: 256 rows x 128B, W: 128 rows x 128B)
    auto issue = [&](int c, int s) {
        const int lb = c * BK;
        const uint32_t buf = smb + (uint32_t)(s * STG_HALVES) * 2u;
#pragma unroll
        for (int i = 0; i < 4; i++) {       // A: 2048 (row,seg) pairs
            const int idx = tid + i * NT;
            const int mrow = idx >> 3, seg = idx & 7;    // mrow 0..255
            const int mod = mrow >> 6, row = mrow & 63;
            const uint32_t dst = buf + 2u * (uint32_t)(mrow * STRIDE + seg * 8);
            CP16(dst, &g_A[mod][b0 + row][lb + seg * 8]);
        }
#pragma unroll
        for (int i = 0; i < 2; i++) {       // W: 1024 (row,seg) pairs
            const int idx = tid + i * NT;
            const int row = idx >> 3, seg = idx & 7;
            const uint32_t dst = buf + 2u * (uint32_t)(W_OFFH + row * STRIDE + seg * 8);
            CP16(dst, &g_W[k0 + row][lb + seg * 8]);
        }
        CP_COMMIT();
    };

    issue(0, 0);
    issue(1, 1);

    for (int c = 0; c < NCHUNK; ++c) {
        CP_WAIT(1);          // group for chunk c complete
        __syncthreads();     // all warps done with chunk c-1 -> stage (c+2)%3 free
        if (c + 2 < NCHUNK) issue(c + 2, (c + 2) % NSTAGE);
        else CP_COMMIT();    // keep group-count semantics exact in the tail

        const uint32_t buf = smb + (uint32_t)((c % NSTAGE) * STG_HALVES) * 2u;
#pragma unroll
        for (int ks = 0; ks < 4; ks++) {
            uint32_t B[8];
            const uint32_t bBase =
                buf + 2u * (uint32_t)(W_OFFH + (wn * 32) * STRIDE + ks * 16 + laneB);
#pragma unroll
            for (int t = 0; t < 2; t++)
                LDSM4(B[4 * t], B[4 * t + 1], B[4 * t + 2], B[4 * t + 3],
                      bBase + 2u * (uint32_t)(t * 16 * STRIDE));
#pragma unroll
            for (int m = 0; m < 4; m++) {
                const uint32_t aBase =
                    buf + 2u * (uint32_t)(m * BM * STRIDE + (wm * 16) * STRIDE
                                          + ks * 16 + laneA);
                uint32_t A0, A1, A2, A3;
                LDSM4(A0, A1, A2, A3, aBase);
#pragma unroll
                for (int nt = 0; nt < 4; nt++)
                    MMA16816(acc[m][nt], A0, A1, A2, A3, B[nt * 2], B[nt * 2 + 1]);
            }
        }
    }

    // ---- epilogue: softmax over modalities + weighted sum + rescale ----
    const int qr = lane >> 2;
    const int qc = (lane & 3) * 2;
#pragma unroll
    for (int rp = 0; rp < 2; rp++) {
        const int row = wm * 16 + qr + rp * 8;
        const float sc_row = g_scal[b0 + row];
        const size_t g = (size_t)(b0 + row) * L_SZ + k0 + wn * 32;
#pragma unroll
        for (int nt = 0; nt < 4; nt++) {
            float2 x[4];
#pragma unroll
            for (int m = 0; m < 4; m++)
                x[m] = *(const float2*)(mods[m] + g + nt * 8 + qc);
            float res[2];
#pragma unroll
            for (int cc = 0; cc < 2; cc++) {
                const float s0 = acc[0][nt][rp * 2 + cc];
                const float s1 = acc[1][nt][rp * 2 + cc];
                const float s2 = acc[2][nt][rp * 2 + cc];
                const float s3 = acc[3][nt][rp * 2 + cc];
                const float mx = fmaxf(fmaxf(s0, s1), fmaxf(s2, s3));
                const float e0 = __expf(s0 - mx);
                const float e1 = __expf(s1 - mx);
                const float e2 = __expf(s2 - mx);
                const float e3 = __expf(s3 - mx);
                const float inv = 1.0f / (e0 + e1 + e2 + e3);
                const float x0 = cc ? x[0].y : x[0].x;
                const float x1 = cc ? x[1].y : x[1].x;
                const float x2 = cc ? x[2].y : x[2].x;
                const float x3 = cc ? x[3].y : x[3].x;
                res[cc] = (e0 * x0 + e1 * x1 + e2 * x2 + e3 * x3) * inv * sc_row;
            }
            *(float2*)(out + g + nt * 8 + qc) = make_float2(res[0], res[1]);
        }
    }
}

extern "C" void kernel_launch(void* const* d_in, const int* in_sizes, int n_in,
                              void* d_out, int out_size)
{
    const float* mods[4] = {nullptr, nullptr, nullptr, nullptr};
    const float* W = nullptr;
    int mi = 0;
    for (int i = 0; i < n_in; i++) {
        if (in_sizes[i] == L_SZ * L_SZ) W = (const float*)d_in[i];
        else if (mi < 4) mods[mi++] = (const float*)d_in[i];
    }
    if (!W) W = (const float*)d_in[n_in - 1];

    cudaFuncSetAttribute(fused_modal_attn_hmma,
                         cudaFuncAttributeMaxDynamicSharedMemorySize, SMEM_BYTES);

    prep_kernel<<<B_SZ + L_SZ, 128>>>(mods[0], mods[1], mods[2], mods[3], W);

    dim3 grid(L_SZ / BN, B_SZ / BM);   // (8, 256): k-tiles fastest -> A L2-coresident
    fused_modal_attn_hmma<<<grid, NT, SMEM_BYTES>>>(
        mods[0], mods[1], mods[2], mods[3], (float*)d_out);
}

// round 10
// speedup vs baseline: 10.9138x; 1.1090x over previous
#include <cuda_runtime.h>
#include <cuda_fp16.h>
#include <cstdint>
#include <cstddef>

#define B_SZ 16384
#define L_SZ 1024
#define BM 32
#define BN 128
#define BK 64
#define NT 256
#define NCHUNK (L_SZ / BK)     // 16
#define NSTAGE 3
#define STRIDE 72              // halves per smem row (144B: conflict-free ldmatrix)
#define A_HALVES (4 * BM * STRIDE)           // 9216 halves per stage (A part)
#define W_OFFH   A_HALVES
#define STG_HALVES (A_HALVES + BN * STRIDE)  // 18432 halves = 36864 B
#define SMEM_BYTES (NSTAGE * STG_HALVES * 2) // 110592 B -> 2 CTAs/SM

// Static scratch (sanctioned: __device__ globals, no runtime alloc)
__device__ __half g_A[4][B_SZ][L_SZ];   // 128 MB fp16 pre-converted modalities
__device__ __half g_W[L_SZ][L_SZ];      // 2 MB fp16 pre-converted W
__device__ float  g_scal[B_SZ];         // per-row rescale factor

__device__ __forceinline__ uint32_t smem_u32(const void* p) {
    uint32_t a;
    asm("{ .reg .u64 t; cvta.to.shared.u64 t, %1; cvt.u32.u64 %0, t; }" : "=r"(a) : "l"(p));
    return a;
}

#define LDSM4(r0, r1, r2, r3, addr)                                        \
    asm volatile("ldmatrix.sync.aligned.m8n8.x4.shared.b16 {%0,%1,%2,%3}, [%4];" \
                 : "=r"(r0), "=r"(r1), "=r"(r2), "=r"(r3) : "r"(addr))

#define MMA16816(d, a0, a1, a2, a3, b0, b1)                                \
    asm volatile("mma.sync.aligned.m16n8k16.row.col.f32.f16.f16.f32 "      \
                 "{%0,%1,%2,%3}, {%4,%5,%6,%7}, {%8,%9}, {%0,%1,%2,%3};"   \
                 : "+f"((d)[0]), "+f"((d)[1]), "+f"((d)[2]), "+f"((d)[3])  \
                 : "r"(a0), "r"(a1), "r"(a2), "r"(a3), "r"(b0), "r"(b1))

#define CP16(dst, src) \
    asm volatile("cp.async.cg.shared.global [%0], [%1], 16;" :: "r"(dst), "l"(src))
#define CP_COMMIT() asm volatile("cp.async.commit_group;" ::: "memory")
#define CP_WAIT(n)  asm volatile("cp.async.wait_group %0;" :: "n"(n) : "memory")

__device__ __forceinline__ uint32_t h2u(__half2 h) {
    return *reinterpret_cast<uint32_t*>(&h);
}

// ---------------------------------------------------------------------------
// Prep: fp32 -> fp16 for the 4 modalities + W; row-sum scaler.
// ---------------------------------------------------------------------------
__global__ __launch_bounds__(128, 8)
void prep_kernel(const float* __restrict__ m0, const float* __restrict__ m1,
                 const float* __restrict__ m2, const float* __restrict__ m3,
                 const float* __restrict__ Wm)
{
    const int t = threadIdx.x;
    const int bid = blockIdx.x;
    if (bid < B_SZ) {
        const float* mods[4] = {m0, m1, m2, m3};
        __shared__ float red[4][4];
#pragma unroll
        for (int m = 0; m < 4; m++) {
            const float* p = mods[m] + (size_t)bid * L_SZ + t * 8;
            const float4 v0 = *(const float4*)p;
            const float4 v1 = *(const float4*)(p + 4);
            float s = ((v0.x + v0.y) + (v0.z + v0.w)) + ((v1.x + v1.y) + (v1.z + v1.w));
            __half2 h0 = __floats2half2_rn(v0.x, v0.y);
            __half2 h1 = __floats2half2_rn(v0.z, v0.w);
            __half2 h2 = __floats2half2_rn(v1.x, v1.y);
            __half2 h3 = __floats2half2_rn(v1.z, v1.w);
            *reinterpret_cast<uint4*>(&g_A[m][bid][t * 8]) =
                make_uint4(h2u(h0), h2u(h1), h2u(h2), h2u(h3));
#pragma unroll
            for (int off = 16; off > 0; off >>= 1)
                s += __shfl_xor_sync(0xffffffffu, s, off);
            if ((t & 31) == 0) red[m][t >> 5] = s;
        }
        __syncthreads();
        if (t == 0) {
            int cnt = 0;
#pragma unroll
            for (int m = 0; m < 4; m++) {
                const float s = (red[m][0] + red[m][1]) + (red[m][2] + red[m][3]);
                cnt += (s == 0.0f) ? 1 : 0;
            }
            g_scal[bid] = (cnt > 0) ? (float)(cnt + 1) : 1.0f;
        }
    } else {
        const int row = bid - B_SZ;
        const float* p = Wm + (size_t)row * L_SZ + t * 8;
        const float4 v0 = *(const float4*)p;
        const float4 v1 = *(const float4*)(p + 4);
        __half2 h0 = __floats2half2_rn(v0.x, v0.y);
        __half2 h1 = __floats2half2_rn(v0.z, v0.w);
        __half2 h2 = __floats2half2_rn(v1.x, v1.y);
        __half2 h3 = __floats2half2_rn(v1.z, v1.w);
        *reinterpret_cast<uint4*>(&g_W[row][t * 8]) =
            make_uint4(h2u(h0), h2u(h1), h2u(h2), h2u(h3));
    }
}

// ---------------------------------------------------------------------------
// Main: fp16 HMMA mainloop, 256 threads (8 warps), 2 CTAs/SM, 3-stage ring.
// Warp tile 16x32: wm = wid&1 (rows), wn = wid>>1 (cols).
// ---------------------------------------------------------------------------
__global__ __launch_bounds__(NT, 2)
void fused_modal_attn_hmma(const float* __restrict__ m0, const float* __restrict__ m1,
                           const float* __restrict__ m2, const float* __restrict__ m3,
                           float* __restrict__ out)
{
    extern __shared__ __align__(16) __half sm[];

    const float* mods[4] = {m0, m1, m2, m3};
    const int tid = threadIdx.x;
    const int wid = tid >> 5;
    const int lane = tid & 31;
    const int b0 = blockIdx.y * BM;
    const int k0 = blockIdx.x * BN;
    const int wm = wid & 1;        // row block: wm*16
    const int wn = wid >> 1;       // col block: wn*32

    // ldmatrix lane offsets (halves)
    const int j = lane >> 3, r = lane & 7;
    const uint32_t laneA = (uint32_t)(((j & 1) * 8 + r) * STRIDE + (j >> 1) * 8);
    const uint32_t laneB = (uint32_t)(((j >> 1) * 8 + r) * STRIDE + (j & 1) * 8);
    const uint32_t smb = smem_u32(sm);

    float acc[4][4][4];   // [mod][n8-tile][frag]
#pragma unroll
    for (int m = 0; m < 4; m++)
#pragma unroll
        for (int nt = 0; nt < 4; nt++)
#pragma unroll
            for (int c = 0; c < 4; c++) acc[m][nt][c] = 0.0f;

    // issue cp.async for chunk c into stage s (A: 128 rows x 128B, W: 128 rows x 128B)
    auto issue = [&](int c, int s) {
        const int lb = c * BK;
        const uint32_t buf = smb + (uint32_t)(s * STG_HALVES) * 2u;
#pragma unroll
        for (int i = 0; i < 4; i++) {       // A: 1024 (row,seg) pairs
            const int idx = tid + i * NT;
            const int mrow = idx >> 3, seg = idx & 7;    // mrow 0..127
            const int mod = mrow >> 5, row = mrow & 31;
            const uint32_t dst = buf + 2u * (uint32_t)(mrow * STRIDE + seg * 8);
            CP16(dst, &g_A[mod][b0 + row][lb + seg * 8]);
        }
#pragma unroll
        for (int i = 0; i < 4; i++) {       // W: 1024 (row,seg) pairs
            const int idx = tid + i * NT;
            const int row = idx >> 3, seg = idx & 7;
            const uint32_t dst = buf + 2u * (uint32_t)(W_OFFH + row * STRIDE + seg * 8);
            CP16(dst, &g_W[k0 + row][lb + seg * 8]);
        }
        CP_COMMIT();
    };

    issue(0, 0);
    issue(1, 1);

    for (int c = 0; c < NCHUNK; ++c) {
        CP_WAIT(1);          // group for chunk c complete
        __syncthreads();     // all warps done with chunk c-1 -> stage (c+2)%3 free
        if (c + 2 < NCHUNK) issue(c + 2, (c + 2) % NSTAGE);
        else CP_COMMIT();    // keep group-count semantics exact in the tail

        const uint32_t buf = smb + (uint32_t)((c % NSTAGE) * STG_HALVES) * 2u;
#pragma unroll
        for (int ks = 0; ks < 4; ks++) {
            uint32_t B[8];
            const uint32_t bBase =
                buf + 2u * (uint32_t)(W_OFFH + (wn * 32) * STRIDE + ks * 16 + laneB);
#pragma unroll
            for (int t = 0; t < 2; t++)
                LDSM4(B[4 * t], B[4 * t + 1], B[4 * t + 2], B[4 * t + 3],
                      bBase + 2u * (uint32_t)(t * 16 * STRIDE));
#pragma unroll
            for (int m = 0; m < 4; m++) {
                const uint32_t aBase =
                    buf + 2u * (uint32_t)(m * BM * STRIDE + (wm * 16) * STRIDE
                                          + ks * 16 + laneA);
                uint32_t A0, A1, A2, A3;
                LDSM4(A0, A1, A2, A3, aBase);
#pragma unroll
                for (int nt = 0; nt < 4; nt++)
                    MMA16816(acc[m][nt], A0, A1, A2, A3, B[nt * 2], B[nt * 2 + 1]);
            }
        }
    }

    // ---- epilogue: softmax over modalities + weighted sum + rescale ----
    const int qr = lane >> 2;
    const int qc = (lane & 3) * 2;
#pragma unroll
    for (int rp = 0; rp < 2; rp++) {
        const int row = wm * 16 + qr + rp * 8;
        const float sc_row = g_scal[b0 + row];
        const size_t g = (size_t)(b0 + row) * L_SZ + k0 + wn * 32;
#pragma unroll
        for (int nt = 0; nt < 4; nt++) {
            float2 x[4];
#pragma unroll
            for (int m = 0; m < 4; m++)
                x[m] = *(const float2*)(mods[m] + g + nt * 8 + qc);
            float res[2];
#pragma unroll
            for (int cc = 0; cc < 2; cc++) {
                const float s0 = acc[0][nt][rp * 2 + cc];
                const float s1 = acc[1][nt][rp * 2 + cc];
                const float s2 = acc[2][nt][rp * 2 + cc];
                const float s3 = acc[3][nt][rp * 2 + cc];
                const float mx = fmaxf(fmaxf(s0, s1), fmaxf(s2, s3));
                const float e0 = __expf(s0 - mx);
                const float e1 = __expf(s1 - mx);
                const float e2 = __expf(s2 - mx);
                const float e3 = __expf(s3 - mx);
                const float inv = 1.0f / (e0 + e1 + e2 + e3);
                const float x0 = cc ? x[0].y : x[0].x;
                const float x1 = cc ? x[1].y : x[1].x;
                const float x2 = cc ? x[2].y : x[2].x;
                const float x3 = cc ? x[3].y : x[3].x;
                res[cc] = (e0 * x0 + e1 * x1 + e2 * x2 + e3 * x3) * inv * sc_row;
            }
            *(float2*)(out + g + nt * 8 + qc) = make_float2(res[0], res[1]);
        }
    }
}

extern "C" void kernel_launch(void* const* d_in, const int* in_sizes, int n_in,
                              void* d_out, int out_size)
{
    const float* mods[4] = {nullptr, nullptr, nullptr, nullptr};
    const float* W = nullptr;
    int mi = 0;
    for (int i = 0; i < n_in; i++) {
        if (in_sizes[i] == L_SZ * L_SZ) W = (const float*)d_in[i];
        else if (mi < 4) mods[mi++] = (const float*)d_in[i];
    }
    if (!W) W = (const float*)d_in[n_in - 1];

    cudaFuncSetAttribute(fused_modal_attn_hmma,
                         cudaFuncAttributeMaxDynamicSharedMemorySize, SMEM_BYTES);

    prep_kernel<<<B_SZ + L_SZ, 128>>>(mods[0], mods[1], mods[2], mods[3], W);

    dim3 grid(L_SZ / BN, B_SZ / BM);   // (8, 512): k-tiles fastest -> A L2-coresident
    fused_modal_attn_hmma<<<grid, NT, SMEM_BYTES>>>(
        mods[0], mods[1], mods[2], mods[3], (float*)d_out);
}

// round 11
// speedup vs baseline: 10.9527x; 1.0036x over previous
#include <cuda_runtime.h>
#include <cuda_fp16.h>
#include <cstdint>
#include <cstddef>

#define B_SZ 16384
#define L_SZ 1024
#define BM 32
#define BN 128
#define BK 64
#define NT 256
#define NCHUNK (L_SZ / BK)     // 16
#define NSTAGE 3
#define STRIDE 72              // halves per smem row (144B: conflict-free ldmatrix)
#define A_HALVES (4 * BM * STRIDE)           // 9216 halves per stage (A part)
#define W_OFFH   A_HALVES
#define STG_HALVES (A_HALVES + BN * STRIDE)  // 18432 halves = 36864 B
#define SMEM_BYTES (NSTAGE * STG_HALVES * 2) // 110592 B -> 2 CTAs/SM

// Static scratch (sanctioned: __device__ globals, no runtime alloc)
__device__ __half g_A[4][B_SZ][L_SZ];   // 128 MB fp16 pre-converted modalities
__device__ __half g_W[L_SZ][L_SZ];      // 2 MB fp16 pre-converted W
__device__ float  g_scal[B_SZ];         // per-row rescale factor

__device__ __forceinline__ uint32_t smem_u32(const void* p) {
    uint32_t a;
    asm("{ .reg .u64 t; cvta.to.shared.u64 t, %1; cvt.u32.u64 %0, t; }" : "=r"(a) : "l"(p));
    return a;
}

#define LDSM4(r0, r1, r2, r3, addr)                                        \
    asm volatile("ldmatrix.sync.aligned.m8n8.x4.shared.b16 {%0,%1,%2,%3}, [%4];" \
                 : "=r"(r0), "=r"(r1), "=r"(r2), "=r"(r3) : "r"(addr))

#define MMA16816(d, a0, a1, a2, a3, b0, b1)                                \
    asm volatile("mma.sync.aligned.m16n8k16.row.col.f32.f16.f16.f32 "      \
                 "{%0,%1,%2,%3}, {%4,%5,%6,%7}, {%8,%9}, {%0,%1,%2,%3};"   \
                 : "+f"((d)[0]), "+f"((d)[1]), "+f"((d)[2]), "+f"((d)[3])  \
                 : "r"(a0), "r"(a1), "r"(a2), "r"(a3), "r"(b0), "r"(b1))

#define CP16(dst, src) \
    asm volatile("cp.async.cg.shared.global [%0], [%1], 16;" :: "r"(dst), "l"(src))
#define CP_COMMIT() asm volatile("cp.async.commit_group;" ::: "memory")
#define CP_WAIT(n)  asm volatile("cp.async.wait_group %0;" :: "n"(n) : "memory")

__device__ __forceinline__ uint32_t h2u(__half2 h) {
    return *reinterpret_cast<uint32_t*>(&h);
}

// ---------------------------------------------------------------------------
// Prep: fp32 -> fp16 for the 4 modalities + W; row-sum scaler.
// ---------------------------------------------------------------------------
__global__ __launch_bounds__(128, 8)
void prep_kernel(const float* __restrict__ m0, const float* __restrict__ m1,
                 const float* __restrict__ m2, const float* __restrict__ m3,
                 const float* __restrict__ Wm)
{
    const int t = threadIdx.x;
    const int bid = blockIdx.x;
    if (bid < B_SZ) {
        const float* mods[4] = {m0, m1, m2, m3};
        __shared__ float red[4][4];
#pragma unroll
        for (int m = 0; m < 4; m++) {
            const float* p = mods[m] + (size_t)bid * L_SZ + t * 8;
            const float4 v0 = *(const float4*)p;
            const float4 v1 = *(const float4*)(p + 4);
            float s = ((v0.x + v0.y) + (v0.z + v0.w)) + ((v1.x + v1.y) + (v1.z + v1.w));
            __half2 h0 = __floats2half2_rn(v0.x, v0.y);
            __half2 h1 = __floats2half2_rn(v0.z, v0.w);
            __half2 h2 = __floats2half2_rn(v1.x, v1.y);
            __half2 h3 = __floats2half2_rn(v1.z, v1.w);
            *reinterpret_cast<uint4*>(&g_A[m][bid][t * 8]) =
                make_uint4(h2u(h0), h2u(h1), h2u(h2), h2u(h3));
#pragma unroll
            for (int off = 16; off > 0; off >>= 1)
                s += __shfl_xor_sync(0xffffffffu, s, off);
            if ((t & 31) == 0) red[m][t >> 5] = s;
        }
        __syncthreads();
        if (t == 0) {
            int cnt = 0;
#pragma unroll
            for (int m = 0; m < 4; m++) {
                const float s = (red[m][0] + red[m][1]) + (red[m][2] + red[m][3]);
                cnt += (s == 0.0f) ? 1 : 0;
            }
            g_scal[bid] = (cnt > 0) ? (float)(cnt + 1) : 1.0f;
        }
    } else {
        const int row = bid - B_SZ;
        const float* p = Wm + (size_t)row * L_SZ + t * 8;
        const float4 v0 = *(const float4*)p;
        const float4 v1 = *(const float4*)(p + 4);
        __half2 h0 = __floats2half2_rn(v0.x, v0.y);
        __half2 h1 = __floats2half2_rn(v0.z, v0.w);
        __half2 h2 = __floats2half2_rn(v1.x, v1.y);
        __half2 h3 = __floats2half2_rn(v1.z, v1.w);
        *reinterpret_cast<uint4*>(&g_W[row][t * 8]) =
            make_uint4(h2u(h0), h2u(h1), h2u(h2), h2u(h3));
    }
}

// ---------------------------------------------------------------------------
// Main: fp16 HMMA mainloop, 256 threads (8 warps), 2 CTAs/SM, 3-stage ring.
// Warp tile 16x32: wm = wid&1 (rows), wn = wid>>1 (cols).
// ---------------------------------------------------------------------------
__global__ __launch_bounds__(NT, 2)
void fused_modal_attn_hmma(const float* __restrict__ m0, const float* __restrict__ m1,
                           const float* __restrict__ m2, const float* __restrict__ m3,
                           float* __restrict__ out)
{
    extern __shared__ __align__(16) __half sm[];

    const float* mods[4] = {m0, m1, m2, m3};
    const int tid = threadIdx.x;
    const int wid = tid >> 5;
    const int lane = tid & 31;
    const int b0 = blockIdx.y * BM;
    const int k0 = blockIdx.x * BN;
    const int wm = wid & 1;        // row block: wm*16
    const int wn = wid >> 1;       // col block: wn*32

    // ldmatrix lane offsets (halves)
    const int j = lane >> 3, r = lane & 7;
    const uint32_t laneA = (uint32_t)(((j & 1) * 8 + r) * STRIDE + (j >> 1) * 8);
    const uint32_t laneB = (uint32_t)(((j >> 1) * 8 + r) * STRIDE + (j & 1) * 8);
    const uint32_t smb = smem_u32(sm);

    float acc[4][4][4];   // [mod][n8-tile][frag]
#pragma unroll
    for (int m = 0; m < 4; m++)
#pragma unroll
        for (int nt = 0; nt < 4; nt++)
#pragma unroll
            for (int c = 0; c < 4; c++) acc[m][nt][c] = 0.0f;

    // issue cp.async for chunk c into stage s (A: 128 rows x 128B, W: 128 rows x 128B)
    auto issue = [&](int c, int s) {
        const int lb = c * BK;
        const uint32_t buf = smb + (uint32_t)(s * STG_HALVES) * 2u;
#pragma unroll
        for (int i = 0; i < 4; i++) {       // A: 1024 (row,seg) pairs
            const int idx = tid + i * NT;
            const int mrow = idx >> 3, seg = idx & 7;    // mrow 0..127
            const int mod = mrow >> 5, row = mrow & 31;
            const uint32_t dst = buf + 2u * (uint32_t)(mrow * STRIDE + seg * 8);
            CP16(dst, &g_A[mod][b0 + row][lb + seg * 8]);
        }
#pragma unroll
        for (int i = 0; i < 4; i++) {       // W: 1024 (row,seg) pairs
            const int idx = tid + i * NT;
            const int row = idx >> 3, seg = idx & 7;
            const uint32_t dst = buf + 2u * (uint32_t)(W_OFFH + row * STRIDE + seg * 8);
            CP16(dst, &g_W[k0 + row][lb + seg * 8]);
        }
        CP_COMMIT();
    };

    issue(0, 0);
    issue(1, 1);

    for (int c = 0; c < NCHUNK; ++c) {
        CP_WAIT(1);          // group for chunk c complete
        __syncthreads();     // all warps done with chunk c-1 -> stage (c+2)%3 free
        if (c + 2 < NCHUNK) issue(c + 2, (c + 2) % NSTAGE);
        else CP_COMMIT();    // keep group-count semantics exact in the tail

        const uint32_t buf = smb + (uint32_t)((c % NSTAGE) * STG_HALVES) * 2u;
#pragma unroll
        for (int ks = 0; ks < 4; ks++) {
            uint32_t B[8];
            const uint32_t bBase =
                buf + 2u * (uint32_t)(W_OFFH + (wn * 32) * STRIDE + ks * 16 + laneB);
#pragma unroll
            for (int t = 0; t < 2; t++)
                LDSM4(B[4 * t], B[4 * t + 1], B[4 * t + 2], B[4 * t + 3],
                      bBase + 2u * (uint32_t)(t * 16 * STRIDE));
#pragma unroll
            for (int m = 0; m < 4; m++) {
                const uint32_t aBase =
                    buf + 2u * (uint32_t)(m * BM * STRIDE + (wm * 16) * STRIDE
                                          + ks * 16 + laneA);
                uint32_t A0, A1, A2, A3;
                LDSM4(A0, A1, A2, A3, aBase);
#pragma unroll
                for (int nt = 0; nt < 4; nt++)
                    MMA16816(acc[m][nt], A0, A1, A2, A3, B[nt * 2], B[nt * 2 + 1]);
            }
        }
    }

    // ---- epilogue: softmax over modalities + weighted sum + rescale ----
    const int qr = lane >> 2;
    const int qc = (lane & 3) * 2;
#pragma unroll
    for (int rp = 0; rp < 2; rp++) {
        const int row = wm * 16 + qr + rp * 8;
        const float sc_row = g_scal[b0 + row];
        const size_t g = (size_t)(b0 + row) * L_SZ + k0 + wn * 32;
#pragma unroll
        for (int nt = 0; nt < 4; nt++) {
            float2 x[4];
#pragma unroll
            for (int m = 0; m < 4; m++)
                x[m] = *(const float2*)(mods[m] + g + nt * 8 + qc);
            float res[2];
#pragma unroll
            for (int cc = 0; cc < 2; cc++) {
                const float s0 = acc[0][nt][rp * 2 + cc];
                const float s1 = acc[1][nt][rp * 2 + cc];
                const float s2 = acc[2][nt][rp * 2 + cc];
                const float s3 = acc[3][nt][rp * 2 + cc];
                const float mx = fmaxf(fmaxf(s0, s1), fmaxf(s2, s3));
                const float e0 = __expf(s0 - mx);
                const float e1 = __expf(s1 - mx);
                const float e2 = __expf(s2 - mx);
                const float e3 = __expf(s3 - mx);
                const float inv = 1.0f / (e0 + e1 + e2 + e3);
                const float x0 = cc ? x[0].y : x[0].x;
                const float x1 = cc ? x[1].y : x[1].x;
                const float x2 = cc ? x[2].y : x[2].x;
                const float x3 = cc ? x[3].y : x[3].x;
                res[cc] = (e0 * x0 + e1 * x1 + e2 * x2 + e3 * x3) * inv * sc_row;
            }
            *(float2*)(out + g + nt * 8 + qc) = make_float2(res[0], res[1]);
        }
    }
}

extern "C" void kernel_launch(void* const* d_in, const int* in_sizes, int n_in,
                              void* d_out, int out_size)
{
    const float* mods[4] = {nullptr, nullptr, nullptr, nullptr};
    const float* W = nullptr;
    int mi = 0;
    for (int i = 0; i < n_in; i++) {
        if (in_sizes[i] == L_SZ * L_SZ) W = (const float*)d_in[i];
        else if (mi < 4) mods[mi++] = (const float*)d_in[i];
    }
    if (!W) W = (const float*)d_in[n_in - 1];

    cudaFuncSetAttribute(fused_modal_attn_hmma,
                         cudaFuncAttributeMaxDynamicSharedMemorySize, SMEM_BYTES);

    prep_kernel<<<B_SZ + L_SZ, 128>>>(mods[0], mods[1], mods[2], mods[3], W);

    dim3 grid(L_SZ / BN, B_SZ / BM);   // (8, 512): k-tiles fastest -> A L2-coresident
    fused_modal_attn_hmma<<<grid, NT, SMEM_BYTES>>>(
        mods[0], mods[1], mods[2], mods[3], (float*)d_out);
}

// round 12
// speedup vs baseline: 11.7140x; 1.0695x over previous
#include <cuda_runtime.h>
#include <cuda_fp16.h>
#include <cstdint>
#include <cstddef>

#define B_SZ 16384
#define L_SZ 1024
#define BM 32
#define BN 128
#define BK 64
#define NT 256
#define NCHUNK (L_SZ / BK)     // 16
#define NSTAGE 3
#define STRIDE 72              // halves per smem row (144B: conflict-free ldmatrix)
#define A_HALVES (4 * BM * STRIDE)           // 9216 halves per stage (A part)
#define W_OFFH   A_HALVES
#define STG_HALVES (A_HALVES + BN * STRIDE)  // 18432 halves = 36864 B
#define SMEM_BYTES (NSTAGE * STG_HALVES * 2) // 110592 B -> 2 CTAs/SM

// Static scratch (sanctioned: __device__ globals, no runtime alloc)
__device__ __half g_A[4][B_SZ][L_SZ];   // 128 MB fp16 pre-converted modalities
__device__ __half g_W[L_SZ][L_SZ];      // 2 MB fp16 pre-converted W
__device__ float  g_scal[B_SZ];         // per-row rescale factor

__device__ __forceinline__ uint32_t smem_u32(const void* p) {
    uint32_t a;
    asm("{ .reg .u64 t; cvta.to.shared.u64 t, %1; cvt.u32.u64 %0, t; }" : "=r"(a) : "l"(p));
    return a;
}

#define LDSM4(r0, r1, r2, r3, addr)                                        \
    asm volatile("ldmatrix.sync.aligned.m8n8.x4.shared.b16 {%0,%1,%2,%3}, [%4];" \
                 : "=r"(r0), "=r"(r1), "=r"(r2), "=r"(r3) : "r"(addr))

#define MMA16816(d, a0, a1, a2, a3, b0, b1)                                \
    asm volatile("mma.sync.aligned.m16n8k16.row.col.f32.f16.f16.f32 "      \
                 "{%0,%1,%2,%3}, {%4,%5,%6,%7}, {%8,%9}, {%0,%1,%2,%3};"   \
                 : "+f"((d)[0]), "+f"((d)[1]), "+f"((d)[2]), "+f"((d)[3])  \
                 : "r"(a0), "r"(a1), "r"(a2), "r"(a3), "r"(b0), "r"(b1))

#define CP16(dst, src) \
    asm volatile("cp.async.cg.shared.global [%0], [%1], 16;" :: "r"(dst), "l"(src))
// Arrive on mbarrier when this thread's prior cp.asyncs complete (no expect-count inc)
#define CP_MBAR_ARRIVE(a) \
    asm volatile("cp.async.mbarrier.arrive.noinc.shared::cta.b64 [%0];" :: "r"(a) : "memory")

#define MBAR_INIT(a, n) \
    asm volatile("mbarrier.init.shared.b64 [%0], %1;" :: "r"(a), "r"((uint32_t)(n)) : "memory")
#define MBAR_ARRIVE(a) \
    asm volatile("mbarrier.arrive.release.cta.shared::cta.b64 _, [%0];" :: "r"(a) : "memory")

#define MBAR_WAIT(a, par) do {                                                            \
    uint32_t _m = (a), _p = (uint32_t)(par), _d;                                          \
    asm volatile("{\n\t.reg .pred p;\n\t"                                                 \
        "mbarrier.try_wait.parity.acquire.cta.shared::cta.b64 p, [%1], %2;\n\t"           \
        "selp.b32 %0,1,0,p;\n\t}" : "=r"(_d) : "r"(_m), "r"(_p) : "memory");              \
    if (!_d) {                                                                            \
        asm volatile("{\n\t.reg .pred P1;\n\t"                                            \
            "W_%=:\n\t"                                                                   \
            "mbarrier.try_wait.parity.acquire.cta.shared::cta.b64 P1, [%0], %1, 0x989680;\n\t" \
            "@P1 bra.uni D_%=;\n\t"                                                       \
            "bra.uni W_%=;\n\t"                                                           \
            "D_%=:\n\t}" :: "r"(_m), "r"(_p) : "memory");                                 \
    }                                                                                     \
} while (0)

__device__ __forceinline__ uint32_t h2u(__half2 h) {
    return *reinterpret_cast<uint32_t*>(&h);
}

// ---------------------------------------------------------------------------
// Prep: fp32 -> fp16 for the 4 modalities + W; row-sum scaler.
// ---------------------------------------------------------------------------
__global__ __launch_bounds__(128, 8)
void prep_kernel(const float* __restrict__ m0, const float* __restrict__ m1,
                 const float* __restrict__ m2, const float* __restrict__ m3,
                 const float* __restrict__ Wm)
{
    const int t = threadIdx.x;
    const int bid = blockIdx.x;
    if (bid < B_SZ) {
        const float* mods[4] = {m0, m1, m2, m3};
        __shared__ float red[4][4];
#pragma unroll
        for (int m = 0; m < 4; m++) {
            const float* p = mods[m] + (size_t)bid * L_SZ + t * 8;
            const float4 v0 = *(const float4*)p;
            const float4 v1 = *(const float4*)(p + 4);
            float s = ((v0.x + v0.y) + (v0.z + v0.w)) + ((v1.x + v1.y) + (v1.z + v1.w));
            __half2 h0 = __floats2half2_rn(v0.x, v0.y);
            __half2 h1 = __floats2half2_rn(v0.z, v0.w);
            __half2 h2 = __floats2half2_rn(v1.x, v1.y);
            __half2 h3 = __floats2half2_rn(v1.z, v1.w);
            *reinterpret_cast<uint4*>(&g_A[m][bid][t * 8]) =
                make_uint4(h2u(h0), h2u(h1), h2u(h2), h2u(h3));
#pragma unroll
            for (int off = 16; off > 0; off >>= 1)
                s += __shfl_xor_sync(0xffffffffu, s, off);
            if ((t & 31) == 0) red[m][t >> 5] = s;
        }
        __syncthreads();
        if (t == 0) {
            int cnt = 0;
#pragma unroll
            for (int m = 0; m < 4; m++) {
                const float s = (red[m][0] + red[m][1]) + (red[m][2] + red[m][3]);
                cnt += (s == 0.0f) ? 1 : 0;
            }
            g_scal[bid] = (cnt > 0) ? (float)(cnt + 1) : 1.0f;
        }
    } else {
        const int row = bid - B_SZ;
        const float* p = Wm + (size_t)row * L_SZ + t * 8;
        const float4 v0 = *(const float4*)p;
        const float4 v1 = *(const float4*)(p + 4);
        __half2 h0 = __floats2half2_rn(v0.x, v0.y);
        __half2 h1 = __floats2half2_rn(v0.z, v0.w);
        __half2 h2 = __floats2half2_rn(v1.x, v1.y);
        __half2 h3 = __floats2half2_rn(v1.z, v1.w);
        *reinterpret_cast<uint4*>(&g_W[row][t * 8]) =
            make_uint4(h2u(h0), h2u(h1), h2u(h2), h2u(h3));
    }
}

// ---------------------------------------------------------------------------
// Main: fp16 HMMA, 8 warps, 2 CTAs/SM, 3-stage ring with per-stage
// full/empty mbarriers (no CTA-wide barrier in the mainloop).
// ---------------------------------------------------------------------------
__global__ __launch_bounds__(NT, 2)
void fused_modal_attn_hmma(const float* __restrict__ m0, const float* __restrict__ m1,
                           const float* __restrict__ m2, const float* __restrict__ m3,
                           float* __restrict__ out)
{
    extern __shared__ __align__(16) __half sm[];
    __shared__ __align__(8) uint64_t mb_full[NSTAGE], mb_empty[NSTAGE];

    const float* mods[4] = {m0, m1, m2, m3};
    const int tid = threadIdx.x;
    const int wid = tid >> 5;
    const int lane = tid & 31;
    const int b0 = blockIdx.y * BM;
    const int k0 = blockIdx.x * BN;
    const int wm = wid & 1;        // row block: wm*16
    const int wn = wid >> 1;       // col block: wn*32

    // ldmatrix lane offsets (halves)
    const int j = lane >> 3, r = lane & 7;
    const uint32_t laneA = (uint32_t)(((j & 1) * 8 + r) * STRIDE + (j >> 1) * 8);
    const uint32_t laneB = (uint32_t)(((j >> 1) * 8 + r) * STRIDE + (j & 1) * 8);
    const uint32_t smb = smem_u32(sm);
    const uint32_t full_a  = smem_u32(mb_full);
    const uint32_t empty_a = smem_u32(mb_empty);

    if (tid == 0) {
#pragma unroll
        for (int s = 0; s < NSTAGE; s++) {
            MBAR_INIT(full_a + 8u * s, NT);    // all 256 threads' cp.async arrivals
            MBAR_INIT(empty_a + 8u * s, 8);    // one arrive per warp
        }
    }
    __syncthreads();

    float acc[4][4][4];   // [mod][n8-tile][frag]
#pragma unroll
    for (int m = 0; m < 4; m++)
#pragma unroll
        for (int nt = 0; nt < 4; nt++)
#pragma unroll
            for (int c = 0; c < 4; c++) acc[m][nt][c] = 0.0f;

    // issue cp.async for chunk c into stage s (A: 128 rows x 128B, W: 128 rows x 128B)
    auto issue = [&](int c, int s) {
        const int lb = c * BK;
        const uint32_t buf = smb + (uint32_t)(s * STG_HALVES) * 2u;
#pragma unroll
        for (int i = 0; i < 4; i++) {       // A: 1024 (row,seg) pairs
            const int idx = tid + i * NT;
            const int mrow = idx >> 3, seg = idx & 7;    // mrow 0..127
            const int mod = mrow >> 5, row = mrow & 31;
            const uint32_t dst = buf + 2u * (uint32_t)(mrow * STRIDE + seg * 8);
            CP16(dst, &g_A[mod][b0 + row][lb + seg * 8]);
        }
#pragma unroll
        for (int i = 0; i < 4; i++) {       // W: 1024 (row,seg) pairs
            const int idx = tid + i * NT;
            const int row = idx >> 3, seg = idx & 7;
            const uint32_t dst = buf + 2u * (uint32_t)(W_OFFH + row * STRIDE + seg * 8);
            CP16(dst, &g_W[k0 + row][lb + seg * 8]);
        }
        CP_MBAR_ARRIVE(full_a + 8u * s);
    };

    issue(0, 0);
    issue(1, 1);

    for (int c = 0; c < NCHUNK; ++c) {
        const int s = c % NSTAGE;
        const int rr = c / NSTAGE;

        // produce chunk c+2 (stage s2): wait for readers of its previous round
        const int cc = c + 2;
        if (cc < NCHUNK) {
            const int s2 = cc % NSTAGE;
            const int r2 = cc / NSTAGE;
            if (r2 > 0) MBAR_WAIT(empty_a + 8u * s2, (r2 - 1) & 1);
            issue(cc, s2);
        }

        // consume chunk c
        MBAR_WAIT(full_a + 8u * s, rr & 1);
        const uint32_t buf = smb + (uint32_t)(s * STG_HALVES) * 2u;
#pragma unroll
        for (int ks = 0; ks < 4; ks++) {
            uint32_t B[8];
            const uint32_t bBase =
                buf + 2u * (uint32_t)(W_OFFH + (wn * 32) * STRIDE + ks * 16 + laneB);
#pragma unroll
            for (int t = 0; t < 2; t++)
                LDSM4(B[4 * t], B[4 * t + 1], B[4 * t + 2], B[4 * t + 3],
                      bBase + 2u * (uint32_t)(t * 16 * STRIDE));
#pragma unroll
            for (int m = 0; m < 4; m++) {
                const uint32_t aBase =
                    buf + 2u * (uint32_t)(m * BM * STRIDE + (wm * 16) * STRIDE
                                          + ks * 16 + laneA);
                uint32_t A0, A1, A2, A3;
                LDSM4(A0, A1, A2, A3, aBase);
#pragma unroll
                for (int nt = 0; nt < 4; nt++)
                    MMA16816(acc[m][nt], A0, A1, A2, A3, B[nt * 2], B[nt * 2 + 1]);
            }
        }
        if (lane == 0) MBAR_ARRIVE(empty_a + 8u * s);   // warp done reading stage s
    }

    // ---- epilogue: softmax over modalities + weighted sum + rescale ----
    const int qr = lane >> 2;
    const int qc = (lane & 3) * 2;
#pragma unroll
    for (int rp = 0; rp < 2; rp++) {
        const int row = wm * 16 + qr + rp * 8;
        const float sc_row = g_scal[b0 + row];
        const size_t g = (size_t)(b0 + row) * L_SZ + k0 + wn * 32;
#pragma unroll
        for (int nt = 0; nt < 4; nt++) {
            float2 x[4];
#pragma unroll
            for (int m = 0; m < 4; m++)
                x[m] = *(const float2*)(mods[m] + g + nt * 8 + qc);
            float res[2];
#pragma unroll
            for (int cc2 = 0; cc2 < 2; cc2++) {
                const float s0 = acc[0][nt][rp * 2 + cc2];
                const float s1 = acc[1][nt][rp * 2 + cc2];
                const float s2 = acc[2][nt][rp * 2 + cc2];
                const float s3 = acc[3][nt][rp * 2 + cc2];
                const float mx = fmaxf(fmaxf(s0, s1), fmaxf(s2, s3));
                const float e0 = __expf(s0 - mx);
                const float e1 = __expf(s1 - mx);
                const float e2 = __expf(s2 - mx);
                const float e3 = __expf(s3 - mx);
                const float inv = 1.0f / (e0 + e1 + e2 + e3);
                const float x0 = cc2 ? x[0].y : x[0].x;
                const float x1 = cc2 ? x[1].y : x[1].x;
                const float x2 = cc2 ? x[2].y : x[2].x;
                const float x3 = cc2 ? x[3].y : x[3].x;
                res[cc2] = (e0 * x0 + e1 * x1 + e2 * x2 + e3 * x3) * inv * sc_row;
            }
            *(float2*)(out + g + nt * 8 + qc) = make_float2(res[0], res[1]);
        }
    }
}

extern "C" void kernel_launch(void* const* d_in, const int* in_sizes, int n_in,
                              void* d_out, int out_size)
{
    const float* mods[4] = {nullptr, nullptr, nullptr, nullptr};
    const float* W = nullptr;
    int mi = 0;
    for (int i = 0; i < n_in; i++) {
        if (in_sizes[i] == L_SZ * L_SZ) W = (const float*)d_in[i];
        else if (mi < 4) mods[mi++] = (const float*)d_in[i];
    }
    if (!W) W = (const float*)d_in[n_in - 1];

    cudaFuncSetAttribute(fused_modal_attn_hmma,
                         cudaFuncAttributeMaxDynamicSharedMemorySize, SMEM_BYTES);

    prep_kernel<<<B_SZ + L_SZ, 128>>>(mods[0], mods[1], mods[2], mods[3], W);

    dim3 grid(L_SZ / BN, B_SZ / BM);   // (8, 512): k-tiles fastest -> A L2-coresident
    fused_modal_attn_hmma<<<grid, NT, SMEM_BYTES>>>(
        mods[0], mods[1], mods[2], mods[3], (float*)d_out);
}

// round 13
// speedup vs baseline: 11.7391x; 1.0021x over previous
#include <cuda_runtime.h>
#include <cuda_fp16.h>
#include <cstdint>
#include <cstddef>

#define B_SZ 16384
#define L_SZ 1024
#define BM 32
#define BN 128
#define BK 64
#define NT 256
#define NCHUNK (L_SZ / BK)     // 16
#define NSTAGE 3
#define STRIDE 72              // halves per smem row (144B: conflict-free ldmatrix)
#define A_HALVES (4 * BM * STRIDE)           // 9216 halves per stage (A part)
#define W_OFFH   A_HALVES
#define STG_HALVES (A_HALVES + BN * STRIDE)  // 18432 halves = 36864 B
#define SMEM_BYTES (NSTAGE * STG_HALVES * 2) // 110592 B -> 2 CTAs/SM

// Static scratch (sanctioned: __device__ globals, no runtime alloc)
__device__ __half g_A[4][B_SZ][L_SZ];   // 128 MB fp16 pre-converted modalities
__device__ __half g_W[L_SZ][L_SZ];      // 2 MB fp16 pre-converted W
__device__ float  g_scal[B_SZ];         // per-row rescale factor

__device__ __forceinline__ uint32_t smem_u32(const void* p) {
    uint32_t a;
    asm("{ .reg .u64 t; cvta.to.shared.u64 t, %1; cvt.u32.u64 %0, t; }" : "=r"(a) : "l"(p));
    return a;
}

#define LDSM4(r0, r1, r2, r3, addr)                                        \
    asm volatile("ldmatrix.sync.aligned.m8n8.x4.shared.b16 {%0,%1,%2,%3}, [%4];" \
                 : "=r"(r0), "=r"(r1), "=r"(r2), "=r"(r3) : "r"(addr))

#define MMA16816(d, a0, a1, a2, a3, b0, b1)                                \
    asm volatile("mma.sync.aligned.m16n8k16.row.col.f32.f16.f16.f32 "      \
                 "{%0,%1,%2,%3}, {%4,%5,%6,%7}, {%8,%9}, {%0,%1,%2,%3};"   \
                 : "+f"((d)[0]), "+f"((d)[1]), "+f"((d)[2]), "+f"((d)[3])  \
                 : "r"(a0), "r"(a1), "r"(a2), "r"(a3), "r"(b0), "r"(b1))

#define CP16(dst, src) \
    asm volatile("cp.async.cg.shared.global [%0], [%1], 16;" :: "r"(dst), "l"(src))
// Arrive on mbarrier when this thread's prior cp.asyncs complete (no expect-count inc)
#define CP_MBAR_ARRIVE(a) \
    asm volatile("cp.async.mbarrier.arrive.noinc.shared::cta.b64 [%0];" :: "r"(a) : "memory")

#define MBAR_INIT(a, n) \
    asm volatile("mbarrier.init.shared.b64 [%0], %1;" :: "r"(a), "r"((uint32_t)(n)) : "memory")
#define MBAR_ARRIVE(a) \
    asm volatile("mbarrier.arrive.release.cta.shared::cta.b64 _, [%0];" :: "r"(a) : "memory")

#define MBAR_WAIT(a, par) do {                                                            \
    uint32_t _m = (a), _p = (uint32_t)(par), _d;                                          \
    asm volatile("{\n\t.reg .pred p;\n\t"                                                 \
        "mbarrier.try_wait.parity.acquire.cta.shared::cta.b64 p, [%1], %2;\n\t"           \
        "selp.b32 %0,1,0,p;\n\t}" : "=r"(_d) : "r"(_m), "r"(_p) : "memory");              \
    if (!_d) {                                                                            \
        asm volatile("{\n\t.reg .pred P1;\n\t"                                            \
            "W_%=:\n\t"                                                                   \
            "mbarrier.try_wait.parity.acquire.cta.shared::cta.b64 P1, [%0], %1, 0x989680;\n\t" \
            "@P1 bra.uni D_%=;\n\t"                                                       \
            "bra.uni W_%=;\n\t"                                                           \
            "D_%=:\n\t}" :: "r"(_m), "r"(_p) : "memory");                                 \
    }                                                                                     \
} while (0)

__device__ __forceinline__ uint32_t h2u(__half2 h) {
    return *reinterpret_cast<uint32_t*>(&h);
}

// ---------------------------------------------------------------------------
// Prep: fp32 -> fp16 for the 4 modalities + W; row-sum scaler.
// ---------------------------------------------------------------------------
__global__ __launch_bounds__(128, 8)
void prep_kernel(const float* __restrict__ m0, const float* __restrict__ m1,
                 const float* __restrict__ m2, const float* __restrict__ m3,
                 const float* __restrict__ Wm)
{
    const int t = threadIdx.x;
    const int bid = blockIdx.x;
    if (bid < B_SZ) {
        const float* mods[4] = {m0, m1, m2, m3};
        __shared__ float red[4][4];
#pragma unroll
        for (int m = 0; m < 4; m++) {
            const float* p = mods[m] + (size_t)bid * L_SZ + t * 8;
            const float4 v0 = *(const float4*)p;
            const float4 v1 = *(const float4*)(p + 4);
            float s = ((v0.x + v0.y) + (v0.z + v0.w)) + ((v1.x + v1.y) + (v1.z + v1.w));
            __half2 h0 = __floats2half2_rn(v0.x, v0.y);
            __half2 h1 = __floats2half2_rn(v0.z, v0.w);
            __half2 h2 = __floats2half2_rn(v1.x, v1.y);
            __half2 h3 = __floats2half2_rn(v1.z, v1.w);
            *reinterpret_cast<uint4*>(&g_A[m][bid][t * 8]) =
                make_uint4(h2u(h0), h2u(h1), h2u(h2), h2u(h3));
#pragma unroll
            for (int off = 16; off > 0; off >>= 1)
                s += __shfl_xor_sync(0xffffffffu, s, off);
            if ((t & 31) == 0) red[m][t >> 5] = s;
        }
        __syncthreads();
        if (t == 0) {
            int cnt = 0;
#pragma unroll
            for (int m = 0; m < 4; m++) {
                const float s = (red[m][0] + red[m][1]) + (red[m][2] + red[m][3]);
                cnt += (s == 0.0f) ? 1 : 0;
            }
            g_scal[bid] = (cnt > 0) ? (float)(cnt + 1) : 1.0f;
        }
    } else {
        const int row = bid - B_SZ;
        const float* p = Wm + (size_t)row * L_SZ + t * 8;
        const float4 v0 = *(const float4*)p;
        const float4 v1 = *(const float4*)(p + 4);
        __half2 h0 = __floats2half2_rn(v0.x, v0.y);
        __half2 h1 = __floats2half2_rn(v0.z, v0.w);
        __half2 h2 = __floats2half2_rn(v1.x, v1.y);
        __half2 h3 = __floats2half2_rn(v1.z, v1.w);
        *reinterpret_cast<uint4*>(&g_W[row][t * 8]) =
            make_uint4(h2u(h0), h2u(h1), h2u(h2), h2u(h3));
    }
}

// ---------------------------------------------------------------------------
// Main: fp16 HMMA, 8 warps, 2 CTAs/SM, 3-stage ring with per-stage
// full/empty mbarriers (no CTA-wide barrier in the mainloop).
// ---------------------------------------------------------------------------
__global__ __launch_bounds__(NT, 2)
void fused_modal_attn_hmma(const float* __restrict__ m0, const float* __restrict__ m1,
                           const float* __restrict__ m2, const float* __restrict__ m3,
                           float* __restrict__ out)
{
    extern __shared__ __align__(16) __half sm[];
    __shared__ __align__(8) uint64_t mb_full[NSTAGE], mb_empty[NSTAGE];

    const float* mods[4] = {m0, m1, m2, m3};
    const int tid = threadIdx.x;
    const int wid = tid >> 5;
    const int lane = tid & 31;
    const int b0 = blockIdx.y * BM;
    const int k0 = blockIdx.x * BN;
    const int wm = wid & 1;        // row block: wm*16
    const int wn = wid >> 1;       // col block: wn*32

    // ldmatrix lane offsets (halves)
    const int j = lane >> 3, r = lane & 7;
    const uint32_t laneA = (uint32_t)(((j & 1) * 8 + r) * STRIDE + (j >> 1) * 8);
    const uint32_t laneB = (uint32_t)(((j >> 1) * 8 + r) * STRIDE + (j & 1) * 8);
    const uint32_t smb = smem_u32(sm);
    const uint32_t full_a  = smem_u32(mb_full);
    const uint32_t empty_a = smem_u32(mb_empty);

    if (tid == 0) {
#pragma unroll
        for (int s = 0; s < NSTAGE; s++) {
            MBAR_INIT(full_a + 8u * s, NT);    // all 256 threads' cp.async arrivals
            MBAR_INIT(empty_a + 8u * s, 8);    // one arrive per warp
        }
    }
    __syncthreads();

    float acc[4][4][4];   // [mod][n8-tile][frag]
#pragma unroll
    for (int m = 0; m < 4; m++)
#pragma unroll
        for (int nt = 0; nt < 4; nt++)
#pragma unroll
            for (int c = 0; c < 4; c++) acc[m][nt][c] = 0.0f;

    // issue cp.async for chunk c into stage s (A: 128 rows x 128B, W: 128 rows x 128B)
    auto issue = [&](int c, int s) {
        const int lb = c * BK;
        const uint32_t buf = smb + (uint32_t)(s * STG_HALVES) * 2u;
#pragma unroll
        for (int i = 0; i < 4; i++) {       // A: 1024 (row,seg) pairs
            const int idx = tid + i * NT;
            const int mrow = idx >> 3, seg = idx & 7;    // mrow 0..127
            const int mod = mrow >> 5, row = mrow & 31;
            const uint32_t dst = buf + 2u * (uint32_t)(mrow * STRIDE + seg * 8);
            CP16(dst, &g_A[mod][b0 + row][lb + seg * 8]);
        }
#pragma unroll
        for (int i = 0; i < 4; i++) {       // W: 1024 (row,seg) pairs
            const int idx = tid + i * NT;
            const int row = idx >> 3, seg = idx & 7;
            const uint32_t dst = buf + 2u * (uint32_t)(W_OFFH + row * STRIDE + seg * 8);
            CP16(dst, &g_W[k0 + row][lb + seg * 8]);
        }
        CP_MBAR_ARRIVE(full_a + 8u * s);
    };

    issue(0, 0);
    issue(1, 1);

    for (int c = 0; c < NCHUNK; ++c) {
        const int s = c % NSTAGE;
        const int rr = c / NSTAGE;

        // produce chunk c+2 (stage s2): wait for readers of its previous round
        const int cc = c + 2;
        if (cc < NCHUNK) {
            const int s2 = cc % NSTAGE;
            const int r2 = cc / NSTAGE;
            if (r2 > 0) MBAR_WAIT(empty_a + 8u * s2, (r2 - 1) & 1);
            issue(cc, s2);
        }

        // consume chunk c
        MBAR_WAIT(full_a + 8u * s, rr & 1);
        const uint32_t buf = smb + (uint32_t)(s * STG_HALVES) * 2u;
#pragma unroll
        for (int ks = 0; ks < 4; ks++) {
            uint32_t B[8];
            const uint32_t bBase =
                buf + 2u * (uint32_t)(W_OFFH + (wn * 32) * STRIDE + ks * 16 + laneB);
#pragma unroll
            for (int t = 0; t < 2; t++)
                LDSM4(B[4 * t], B[4 * t + 1], B[4 * t + 2], B[4 * t + 3],
                      bBase + 2u * (uint32_t)(t * 16 * STRIDE));
#pragma unroll
            for (int m = 0; m < 4; m++) {
                const uint32_t aBase =
                    buf + 2u * (uint32_t)(m * BM * STRIDE + (wm * 16) * STRIDE
                                          + ks * 16 + laneA);
                uint32_t A0, A1, A2, A3;
                LDSM4(A0, A1, A2, A3, aBase);
#pragma unroll
                for (int nt = 0; nt < 4; nt++)
                    MMA16816(acc[m][nt], A0, A1, A2, A3, B[nt * 2], B[nt * 2 + 1]);
            }
        }
        if (lane == 0) MBAR_ARRIVE(empty_a + 8u * s);   // warp done reading stage s
    }

    // ---- epilogue: softmax over modalities + weighted sum + rescale ----
    const int qr = lane >> 2;
    const int qc = (lane & 3) * 2;
#pragma unroll
    for (int rp = 0; rp < 2; rp++) {
        const int row = wm * 16 + qr + rp * 8;
        const float sc_row = g_scal[b0 + row];
        const size_t g = (size_t)(b0 + row) * L_SZ + k0 + wn * 32;
#pragma unroll
        for (int nt = 0; nt < 4; nt++) {
            float2 x[4];
#pragma unroll
            for (int m = 0; m < 4; m++)
                x[m] = *(const float2*)(mods[m] + g + nt * 8 + qc);
            float res[2];
#pragma unroll
            for (int cc2 = 0; cc2 < 2; cc2++) {
                const float s0 = acc[0][nt][rp * 2 + cc2];
                const float s1 = acc[1][nt][rp * 2 + cc2];
                const float s2 = acc[2][nt][rp * 2 + cc2];
                const float s3 = acc[3][nt][rp * 2 + cc2];
                const float mx = fmaxf(fmaxf(s0, s1), fmaxf(s2, s3));
                const float e0 = __expf(s0 - mx);
                const float e1 = __expf(s1 - mx);
                const float e2 = __expf(s2 - mx);
                const float e3 = __expf(s3 - mx);
                const float inv = 1.0f / (e0 + e1 + e2 + e3);
                const float x0 = cc2 ? x[0].y : x[0].x;
                const float x1 = cc2 ? x[1].y : x[1].x;
                const float x2 = cc2 ? x[2].y : x[2].x;
                const float x3 = cc2 ? x[3].y : x[3].x;
                res[cc2] = (e0 * x0 + e1 * x1 + e2 * x2 + e3 * x3) * inv * sc_row;
            }
            *(float2*)(out + g + nt * 8 + qc) = make_float2(res[0], res[1]);
        }
    }
}

extern "C" void kernel_launch(void* const* d_in, const int* in_sizes, int n_in,
                              void* d_out, int out_size)
{
    const float* mods[4] = {nullptr, nullptr, nullptr, nullptr};
    const float* W = nullptr;
    int mi = 0;
    for (int i = 0; i < n_in; i++) {
        if (in_sizes[i] == L_SZ * L_SZ) W = (const float*)d_in[i];
        else if (mi < 4) mods[mi++] = (const float*)d_in[i];
    }
    if (!W) W = (const float*)d_in[n_in - 1];

    cudaFuncSetAttribute(fused_modal_attn_hmma,
                         cudaFuncAttributeMaxDynamicSharedMemorySize, SMEM_BYTES);

    prep_kernel<<<B_SZ + L_SZ, 128>>>(mods[0], mods[1], mods[2], mods[3], W);

    dim3 grid(L_SZ / BN, B_SZ / BM);   // (8, 512): k-tiles fastest -> A L2-coresident
    fused_modal_attn_hmma<<<grid, NT, SMEM_BYTES>>>(
        mods[0], mods[1], mods[2], mods[3], (float*)d_out);
}

// round 16
// speedup vs baseline: 12.6367x; 1.0765x over previous
#include <cuda_runtime.h>
#include <cuda_fp16.h>
#include <cstdint>
#include <cstddef>

#define B_SZ 16384
#define L_SZ 1024
#define BM 32
#define BN 128
#define BK 64
#define NT 256
#define NCHUNK (L_SZ / BK)     // 16
#define NSTAGE 3
#define STRIDE 72              // halves per smem row (144B: conflict-free ldmatrix)
#define A_HALVES (4 * BM * STRIDE)           // 9216 halves per stage (A part)
#define W_OFFH   A_HALVES
#define STG_HALVES (A_HALVES + BN * STRIDE)  // 18432 halves = 36864 B
#define SMEM_BYTES (NSTAGE * STG_HALVES * 2) // 110592 B -> 2 CTAs/SM

// Static scratch (sanctioned: __device__ globals, no runtime alloc)
__device__ __half g_A[4][B_SZ][L_SZ];   // 128 MB fp16 pre-converted modalities
__device__ __half g_W[L_SZ][L_SZ];      // 2 MB fp16 pre-converted W
__device__ float  g_scal[B_SZ];         // per-row rescale factor

__device__ __forceinline__ uint32_t smem_u32(const void* p) {
    uint32_t a;
    asm("{ .reg .u64 t; cvta.to.shared.u64 t, %1; cvt.u32.u64 %0, t; }" : "=r"(a) : "l"(p));
    return a;
}

#define LDSM4(r0, r1, r2, r3, addr)                                        \
    asm volatile("ldmatrix.sync.aligned.m8n8.x4.shared.b16 {%0,%1,%2,%3}, [%4];" \
                 : "=r"(r0), "=r"(r1), "=r"(r2), "=r"(r3) : "r"(addr))

#define MMA16816(d, a0, a1, a2, a3, b0, b1)                                \
    asm volatile("mma.sync.aligned.m16n8k16.row.col.f32.f16.f16.f32 "      \
                 "{%0,%1,%2,%3}, {%4,%5,%6,%7}, {%8,%9}, {%0,%1,%2,%3};"   \
                 : "+f"((d)[0]), "+f"((d)[1]), "+f"((d)[2]), "+f"((d)[3])  \
                 : "r"(a0), "r"(a1), "r"(a2), "r"(a3), "r"(b0), "r"(b1))

#define CP16(dst, src) \
    asm volatile("cp.async.cg.shared.global [%0], [%1], 16;" :: "r"(dst), "l"(src))
// Arrive on mbarrier when this thread's prior cp.asyncs complete (no expect-count inc)
#define CP_MBAR_ARRIVE(a) \
    asm volatile("cp.async.mbarrier.arrive.noinc.shared::cta.b64 [%0];" :: "r"(a) : "memory")

#define MBAR_INIT(a, n) \
    asm volatile("mbarrier.init.shared.b64 [%0], %1;" :: "r"(a), "r"((uint32_t)(n)) : "memory")
#define MBAR_ARRIVE(a) \
    asm volatile("mbarrier.arrive.release.cta.shared::cta.b64 _, [%0];" :: "r"(a) : "memory")

// Consumer wait: acquire (orders subsequent LDSM reads)
#define MBAR_WAIT(a, par) do {                                                            \
    uint32_t _m = (a), _p = (uint32_t)(par), _d;                                          \
    asm volatile("{\n\t.reg .pred p;\n\t"                                                 \
        "mbarrier.try_wait.parity.acquire.cta.shared::cta.b64 p, [%1], %2;\n\t"           \
        "selp.b32 %0,1,0,p;\n\t}" : "=r"(_d) : "r"(_m), "r"(_p) : "memory");              \
    if (!_d) {                                                                            \
        asm volatile("{\n\t.reg .pred P1;\n\t"                                            \
            "W_%=:\n\t"                                                                   \
            "mbarrier.try_wait.parity.acquire.cta.shared::cta.b64 P1, [%0], %1, 0x989680;\n\t" \
            "@P1 bra.uni D_%=;\n\t"                                                       \
            "bra.uni W_%=;\n\t"                                                           \
            "D_%=:\n\t}" :: "r"(_m), "r"(_p) : "memory");                                 \
    }                                                                                     \
} while (0)

// Producer wait: relaxed (post-wait writes are async-proxy cp.async only)
#define MBAR_WAIT_RLX(a, par) do {                                                        \
    uint32_t _m = (a), _p = (uint32_t)(par), _d;                                          \
    asm volatile("{\n\t.reg .pred p;\n\t"                                                 \
        "mbarrier.try_wait.parity.relaxed.cta.shared::cta.b64 p, [%1], %2;\n\t"           \
        "selp.b32 %0,1,0,p;\n\t}" : "=r"(_d) : "r"(_m), "r"(_p) : "memory");              \
    if (!_d) {                                                                            \
        asm volatile("{\n\t.reg .pred P1;\n\t"                                            \
            "W_%=:\n\t"                                                                   \
            "mbarrier.try_wait.parity.relaxed.cta.shared::cta.b64 P1, [%0], %1, 0x989680;\n\t" \
            "@P1 bra.uni D_%=;\n\t"                                                       \
            "bra.uni W_%=;\n\t"                                                           \
            "D_%=:\n\t}" :: "r"(_m), "r"(_p) : "memory");                                 \
    }                                                                                     \
} while (0)

__device__ __forceinline__ uint32_t h2u(__half2 h) {
    return *reinterpret_cast<uint32_t*>(&h);
}

// ---------------------------------------------------------------------------
// Prep: fp32 -> fp16 for the 4 modalities + W; row-sum scaler.
// ---------------------------------------------------------------------------
__global__ __launch_bounds__(128, 8)
void prep_kernel(const float* __restrict__ m0, const float* __restrict__ m1,
                 const float* __restrict__ m2, const float* __restrict__ m3,
                 const float* __restrict__ Wm)
{
    const int t = threadIdx.x;
    const int bid = blockIdx.x;
    if (bid < B_SZ) {
        const float* mods[4] = {m0, m1, m2, m3};
        __shared__ float red[4][4];
#pragma unroll
        for (int m = 0; m < 4; m++) {
            const float* p = mods[m] + (size_t)bid * L_SZ + t * 8;
            const float4 v0 = *(const float4*)p;
            const float4 v1 = *(const float4*)(p + 4);
            float s = ((v0.x + v0.y) + (v0.z + v0.w)) + ((v1.x + v1.y) + (v1.z + v1.w));
            __half2 h0 = __floats2half2_rn(v0.x, v0.y);
            __half2 h1 = __floats2half2_rn(v0.z, v0.w);
            __half2 h2 = __floats2half2_rn(v1.x, v1.y);
            __half2 h3 = __floats2half2_rn(v1.z, v1.w);
            *reinterpret_cast<uint4*>(&g_A[m][bid][t * 8]) =
                make_uint4(h2u(h0), h2u(h1), h2u(h2), h2u(h3));
#pragma unroll
            for (int off = 16; off > 0; off >>= 1)
                s += __shfl_xor_sync(0xffffffffu, s, off);
            if ((t & 31) == 0) red[m][t >> 5] = s;
        }
        __syncthreads();
        if (t == 0) {
            int cnt = 0;
#pragma unroll
            for (int m = 0; m < 4; m++) {
                const float s = (red[m][0] + red[m][1]) + (red[m][2] + red[m][3]);
                cnt += (s == 0.0f) ? 1 : 0;
            }
            g_scal[bid] = (cnt > 0) ? (float)(cnt + 1) : 1.0f;
        }
    } else {
        const int row = bid - B_SZ;
        const float* p = Wm + (size_t)row * L_SZ + t * 8;
        const float4 v0 = *(const float4*)p;
        const float4 v1 = *(const float4*)(p + 4);
        __half2 h0 = __floats2half2_rn(v0.x, v0.y);
        __half2 h1 = __floats2half2_rn(v0.z, v0.w);
        __half2 h2 = __floats2half2_rn(v1.x, v1.y);
        __half2 h3 = __floats2half2_rn(v1.z, v1.w);
        *reinterpret_cast<uint4*>(&g_W[row][t * 8]) =
            make_uint4(h2u(h0), h2u(h1), h2u(h2), h2u(h3));
    }
}

// ---------------------------------------------------------------------------
// Main: fp16 HMMA, 8 warps, 2 CTAs/SM, 3-stage mbarrier ring,
// strength-reduced cp.async addressing, MMA-first chunk ordering.
// ---------------------------------------------------------------------------
__global__ __launch_bounds__(NT, 2)
void fused_modal_attn_hmma(const float* __restrict__ m0, const float* __restrict__ m1,
                           const float* __restrict__ m2, const float* __restrict__ m3,
                           float* __restrict__ out)
{
    extern __shared__ __align__(16) __half sm[];
    __shared__ __align__(8) uint64_t mb_full[NSTAGE], mb_empty[NSTAGE];

    const float* mods[4] = {m0, m1, m2, m3};
    const int tid = threadIdx.x;
    const int wid = tid >> 5;
    const int lane = tid & 31;
    const int b0 = blockIdx.y * BM;
    const int k0 = blockIdx.x * BN;
    const int wm = wid & 1;        // row block: wm*16
    const int wn = wid >> 1;       // col block: wn*32

    // ldmatrix lane offsets (halves)
    const int j = lane >> 3, r = lane & 7;
    const uint32_t laneA = (uint32_t)(((j & 1) * 8 + r) * STRIDE + (j >> 1) * 8);
    const uint32_t laneB = (uint32_t)(((j >> 1) * 8 + r) * STRIDE + (j & 1) * 8);
    const uint32_t smb = smem_u32(sm);
    const uint32_t full_a  = smem_u32(mb_full);
    const uint32_t empty_a = smem_u32(mb_empty);

    if (tid == 0) {
#pragma unroll
        for (int s = 0; s < NSTAGE; s++) {
            MBAR_INIT(full_a + 8u * s, NT);    // all 256 threads' cp.async arrivals
            MBAR_INIT(empty_a + 8u * s, 8);    // one arrive per warp
        }
    }
    __syncthreads();

    // Strength-reduced copy addressing:
    // A copy i (i=0..3): mod=i, row=tid>>3, seg=tid&7 (BM=32, NT=256)
    // W copy i:          row=(tid>>3)+32*i, seg=tid&7
    const int arow = tid >> 3, aseg = tid & 7;
    const __half* __restrict__ srcA0 = &g_A[0][b0 + arow][aseg * 8];
    const __half* __restrict__ srcW0 = &g_W[k0 + arow][aseg * 8];
    const uint32_t dstA0 = 2u * (uint32_t)(arow * STRIDE + aseg * 8);
    const uint32_t dstW0 = 2u * (uint32_t)(W_OFFH + arow * STRIDE + aseg * 8);
    const uint32_t dstStep = 2u * (uint32_t)(32 * STRIDE);       // per-i dst stride
    const size_t srcAStep = (size_t)B_SZ * L_SZ;                 // per-i A src stride (mod)
    const size_t srcWStep = (size_t)32 * L_SZ;                   // per-i W src stride (rows)

    float acc[4][4][4];   // [mod][n8-tile][frag]
#pragma unroll
    for (int m = 0; m < 4; m++)
#pragma unroll
        for (int nt = 0; nt < 4; nt++)
#pragma unroll
            for (int c = 0; c < 4; c++) acc[m][nt][c] = 0.0f;

    auto issue = [&](int c, int s) {
        const uint32_t buf = smb + (uint32_t)(s * STG_HALVES) * 2u;
        const __half* sA = srcA0 + c * BK;
        const __half* sW = srcW0 + c * BK;
#pragma unroll
        for (int i = 0; i < 4; i++)
            CP16(buf + dstA0 + (uint32_t)i * dstStep, sA + (size_t)i * srcAStep);
#pragma unroll
        for (int i = 0; i < 4; i++)
            CP16(buf + dstW0 + (uint32_t)i * dstStep, sW + (size_t)i * srcWStep);
        CP_MBAR_ARRIVE(full_a + 8u * s);
    };

    issue(0, 0);
    issue(1, 1);

    for (int c = 0; c < NCHUNK; ++c) {
        const int s = c % NSTAGE;
        const int rr = c / NSTAGE;

        // consume chunk c (first half: ks 0-1)
        MBAR_WAIT(full_a + 8u * s, rr & 1);
        const uint32_t buf = smb + (uint32_t)(s * STG_HALVES) * 2u;

#pragma unroll
        for (int half = 0; half < 2; half++) {
            if (half == 1) {
                // produce chunk c+2 between the two MMA halves
                const int cc = c + 2;
                if (cc < NCHUNK) {
                    const int s2 = cc % NSTAGE;
                    const int r2 = cc / NSTAGE;
                    if (r2 > 0) MBAR_WAIT_RLX(empty_a + 8u * s2, (r2 - 1) & 1);
                    issue(cc, s2);
                }
            }
#pragma unroll
            for (int kq = 0; kq < 2; kq++) {
                const int ks = half * 2 + kq;
                uint32_t B[8];
                const uint32_t bBase =
                    buf + 2u * (uint32_t)(W_OFFH + (wn * 32) * STRIDE + ks * 16 + laneB);
#pragma unroll
                for (int t = 0; t < 2; t++)
                    LDSM4(B[4 * t], B[4 * t + 1], B[4 * t + 2], B[4 * t + 3],
                          bBase + 2u * (uint32_t)(t * 16 * STRIDE));
#pragma unroll
                for (int m = 0; m < 4; m++) {
                    const uint32_t aBase =
                        buf + 2u * (uint32_t)(m * BM * STRIDE + (wm * 16) * STRIDE
                                              + ks * 16 + laneA);
                    uint32_t A0, A1, A2, A3;
                    LDSM4(A0, A1, A2, A3, aBase);
#pragma unroll
                    for (int nt = 0; nt < 4; nt++)
                        MMA16816(acc[m][nt], A0, A1, A2, A3, B[nt * 2], B[nt * 2 + 1]);
                }
            }
        }
        if (lane == 0) MBAR_ARRIVE(empty_a + 8u * s);   // warp done reading stage s
    }

    // ---- epilogue: softmax over modalities + weighted sum + rescale ----
    const int qr = lane >> 2;
    const int qc = (lane & 3) * 2;
#pragma unroll
    for (int rp = 0; rp < 2; rp++) {
        const int row = wm * 16 + qr + rp * 8;
        const float sc_row = g_scal[b0 + row];
        const size_t g = (size_t)(b0 + row) * L_SZ + k0 + wn * 32;
#pragma unroll
        for (int nt = 0; nt < 4; nt++) {
            float2 x[4];
#pragma unroll
            for (int m = 0; m < 4; m++)
                x[m] = *(const float2*)(mods[m] + g + nt * 8 + qc);
            float res[2];
#pragma unroll
            for (int cc2 = 0; cc2 < 2; cc2++) {
                const float s0 = acc[0][nt][rp * 2 + cc2];
                const float s1 = acc[1][nt][rp * 2 + cc2];
                const float s2 = acc[2][nt][rp * 2 + cc2];
                const float s3 = acc[3][nt][rp * 2 + cc2];
                const float mx = fmaxf(fmaxf(s0, s1), fmaxf(s2, s3));
                const float e0 = __expf(s0 - mx);
                const float e1 = __expf(s1 - mx);
                const float e2 = __expf(s2 - mx);
                const float e3 = __expf(s3 - mx);
                const float inv = 1.0f / (e0 + e1 + e2 + e3);
                const float x0 = cc2 ? x[0].y : x[0].x;
                const float x1 = cc2 ? x[1].y : x[1].x;
                const float x2 = cc2 ? x[2].y : x[2].x;
                const float x3 = cc2 ? x[3].y : x[3].x;
                res[cc2] = (e0 * x0 + e1 * x1 + e2 * x2 + e3 * x3) * inv * sc_row;
            }
            *(float2*)(out + g + nt * 8 + qc) = make_float2(res[0], res[1]);
        }
    }
}

extern "C" void kernel_launch(void* const* d_in, const int* in_sizes, int n_in,
                              void* d_out, int out_size)
{
    const float* mods[4] = {nullptr, nullptr, nullptr, nullptr};
    const float* W = nullptr;
    int mi = 0;
    for (int i = 0; i < n_in; i++) {
        if (in_sizes[i] == L_SZ * L_SZ) W = (const float*)d_in[i];
        else if (mi < 4) mods[mi++] = (const float*)d_in[i];
    }
    if (!W) W = (const float*)d_in[n_in - 1];

    cudaFuncSetAttribute(fused_modal_attn_hmma,
                         cudaFuncAttributeMaxDynamicSharedMemorySize, SMEM_BYTES);

    prep_kernel<<<B_SZ + L_SZ, 128>>>(mods[0], mods[1], mods[2], mods[3], W);

    dim3 grid(L_SZ / BN, B_SZ / BM);   // (8, 512): k-tiles fastest -> A L2-coresident
    fused_modal_attn_hmma<<<grid, NT, SMEM_BYTES>>>(
        mods[0], mods[1], mods[2], mods[3], (float*)d_out);
}

// round 17
// speedup vs baseline: 13.1211x; 1.0383x over previous
#include <cuda_runtime.h>
#include <cuda_fp16.h>
#include <cstdint>
#include <cstddef>

#define B_SZ 16384
#define L_SZ 1024
#define BM 32
#define BN 128
#define BK 64
#define NT 256
#define NCHUNK (L_SZ / BK)     // 16
#define NSTAGE 3
#define STRIDE 72              // halves per smem row (144B: conflict-free ldmatrix)
#define A_HALVES (4 * BM * STRIDE)           // 9216 halves per stage (A part)
#define W_OFFH   A_HALVES
#define STG_HALVES (A_HALVES + BN * STRIDE)  // 18432 halves = 36864 B
#define SMEM_BYTES (NSTAGE * STG_HALVES * 2) // 110592 B -> 2 CTAs/SM

// Static scratch (sanctioned: __device__ globals, no runtime alloc)
__device__ __half g_A[4][B_SZ][L_SZ];   // 128 MB fp16 pre-converted modalities
__device__ __half g_W[L_SZ][L_SZ];      // 2 MB fp16 pre-converted W
__device__ float  g_scal[B_SZ];         // per-row rescale factor

__device__ __forceinline__ uint32_t smem_u32(const void* p) {
    uint32_t a;
    asm("{ .reg .u64 t; cvta.to.shared.u64 t, %1; cvt.u32.u64 %0, t; }" : "=r"(a) : "l"(p));
    return a;
}

#define LDSM4(r0, r1, r2, r3, addr)                                        \
    asm volatile("ldmatrix.sync.aligned.m8n8.x4.shared.b16 {%0,%1,%2,%3}, [%4];" \
                 : "=r"(r0), "=r"(r1), "=r"(r2), "=r"(r3) : "r"(addr))

#define MMA16816(d, a0, a1, a2, a3, b0, b1)                                \
    asm volatile("mma.sync.aligned.m16n8k16.row.col.f32.f16.f16.f32 "      \
                 "{%0,%1,%2,%3}, {%4,%5,%6,%7}, {%8,%9}, {%0,%1,%2,%3};"   \
                 : "+f"((d)[0]), "+f"((d)[1]), "+f"((d)[2]), "+f"((d)[3])  \
                 : "r"(a0), "r"(a1), "r"(a2), "r"(a3), "r"(b0), "r"(b1))

#define CP16(dst, src) \
    asm volatile("cp.async.cg.shared.global [%0], [%1], 16;" :: "r"(dst), "l"(src))
// Arrive on mbarrier when this thread's prior cp.asyncs complete (no expect-count inc)
#define CP_MBAR_ARRIVE(a) \
    asm volatile("cp.async.mbarrier.arrive.noinc.shared::cta.b64 [%0];" :: "r"(a) : "memory")

#define MBAR_INIT(a, n) \
    asm volatile("mbarrier.init.shared.b64 [%0], %1;" :: "r"(a), "r"((uint32_t)(n)) : "memory")
#define MBAR_ARRIVE(a) \
    asm volatile("mbarrier.arrive.release.cta.shared::cta.b64 _, [%0];" :: "r"(a) : "memory")

// Consumer wait: acquire (orders subsequent LDSM reads)
#define MBAR_WAIT(a, par) do {                                                            \
    uint32_t _m = (a), _p = (uint32_t)(par), _d;                                          \
    asm volatile("{\n\t.reg .pred p;\n\t"                                                 \
        "mbarrier.try_wait.parity.acquire.cta.shared::cta.b64 p, [%1], %2;\n\t"           \
        "selp.b32 %0,1,0,p;\n\t}" : "=r"(_d) : "r"(_m), "r"(_p) : "memory");              \
    if (!_d) {                                                                            \
        asm volatile("{\n\t.reg .pred P1;\n\t"                                            \
            "W_%=:\n\t"                                                                   \
            "mbarrier.try_wait.parity.acquire.cta.shared::cta.b64 P1, [%0], %1, 0x989680;\n\t" \
            "@P1 bra.uni D_%=;\n\t"                                                       \
            "bra.uni W_%=;\n\t"                                                           \
            "D_%=:\n\t}" :: "r"(_m), "r"(_p) : "memory");                                 \
    }                                                                                     \
} while (0)

// Producer wait: relaxed (post-wait writes are async-proxy cp.async only)
#define MBAR_WAIT_RLX(a, par) do {                                                        \
    uint32_t _m = (a), _p = (uint32_t)(par), _d;                                          \
    asm volatile("{\n\t.reg .pred p;\n\t"                                                 \
        "mbarrier.try_wait.parity.relaxed.cta.shared::cta.b64 p, [%1], %2;\n\t"           \
        "selp.b32 %0,1,0,p;\n\t}" : "=r"(_d) : "r"(_m), "r"(_p) : "memory");              \
    if (!_d) {                                                                            \
        asm volatile("{\n\t.reg .pred P1;\n\t"                                            \
            "W_%=:\n\t"                                                                   \
            "mbarrier.try_wait.parity.relaxed.cta.shared::cta.b64 P1, [%0], %1, 0x989680;\n\t" \
            "@P1 bra.uni D_%=;\n\t"                                                       \
            "bra.uni W_%=;\n\t"                                                           \
            "D_%=:\n\t}" :: "r"(_m), "r"(_p) : "memory");                                 \
    }                                                                                     \
} while (0)

__device__ __forceinline__ uint32_t h2u(__half2 h) {
    return *reinterpret_cast<uint32_t*>(&h);
}

// ---------------------------------------------------------------------------
// Prep: fp32 -> fp16 for the 4 modalities + W; row-sum scaler.
// ---------------------------------------------------------------------------
__global__ __launch_bounds__(128, 8)
void prep_kernel(const float* __restrict__ m0, const float* __restrict__ m1,
                 const float* __restrict__ m2, const float* __restrict__ m3,
                 const float* __restrict__ Wm)
{
    const int t = threadIdx.x;
    const int bid = blockIdx.x;
    if (bid < B_SZ) {
        const float* mods[4] = {m0, m1, m2, m3};
        __shared__ float red[4][4];
#pragma unroll
        for (int m = 0; m < 4; m++) {
            const float* p = mods[m] + (size_t)bid * L_SZ + t * 8;
            const float4 v0 = *(const float4*)p;
            const float4 v1 = *(const float4*)(p + 4);
            float s = ((v0.x + v0.y) + (v0.z + v0.w)) + ((v1.x + v1.y) + (v1.z + v1.w));
            __half2 h0 = __floats2half2_rn(v0.x, v0.y);
            __half2 h1 = __floats2half2_rn(v0.z, v0.w);
            __half2 h2 = __floats2half2_rn(v1.x, v1.y);
            __half2 h3 = __floats2half2_rn(v1.z, v1.w);
            *reinterpret_cast<uint4*>(&g_A[m][bid][t * 8]) =
                make_uint4(h2u(h0), h2u(h1), h2u(h2), h2u(h3));
#pragma unroll
            for (int off = 16; off > 0; off >>= 1)
                s += __shfl_xor_sync(0xffffffffu, s, off);
            if ((t & 31) == 0) red[m][t >> 5] = s;
        }
        __syncthreads();
        if (t == 0) {
            int cnt = 0;
#pragma unroll
            for (int m = 0; m < 4; m++) {
                const float s = (red[m][0] + red[m][1]) + (red[m][2] + red[m][3]);
                cnt += (s == 0.0f) ? 1 : 0;
            }
            g_scal[bid] = (cnt > 0) ? (float)(cnt + 1) : 1.0f;
        }
    } else {
        const int row = bid - B_SZ;
        const float* p = Wm + (size_t)row * L_SZ + t * 8;
        const float4 v0 = *(const float4*)p;
        const float4 v1 = *(const float4*)(p + 4);
        __half2 h0 = __floats2half2_rn(v0.x, v0.y);
        __half2 h1 = __floats2half2_rn(v0.z, v0.w);
        __half2 h2 = __floats2half2_rn(v1.x, v1.y);
        __half2 h3 = __floats2half2_rn(v1.z, v1.w);
        *reinterpret_cast<uint4*>(&g_W[row][t * 8]) =
            make_uint4(h2u(h0), h2u(h1), h2u(h2), h2u(h3));
    }
}

// ---------------------------------------------------------------------------
// Main: fp16 HMMA, 8 warps, 2 CTAs/SM, 3-stage mbarrier ring.
// Chunk loop FULLY UNROLLED: stage indices/parities/addresses compile-time.
// ---------------------------------------------------------------------------
__global__ __launch_bounds__(NT, 2)
void fused_modal_attn_hmma(const float* __restrict__ m0, const float* __restrict__ m1,
                           const float* __restrict__ m2, const float* __restrict__ m3,
                           float* __restrict__ out)
{
    extern __shared__ __align__(16) __half sm[];
    __shared__ __align__(8) uint64_t mb_full[NSTAGE], mb_empty[NSTAGE];

    const float* mods[4] = {m0, m1, m2, m3};
    const int tid = threadIdx.x;
    const int wid = tid >> 5;
    const int lane = tid & 31;
    const int b0 = blockIdx.y * BM;
    const int k0 = blockIdx.x * BN;
    const int wm = wid & 1;        // row block: wm*16
    const int wn = wid >> 1;       // col block: wn*32

    // ldmatrix lane offsets (halves)
    const int j = lane >> 3, r = lane & 7;
    const uint32_t laneA = (uint32_t)(((j & 1) * 8 + r) * STRIDE + (j >> 1) * 8);
    const uint32_t laneB = (uint32_t)(((j >> 1) * 8 + r) * STRIDE + (j & 1) * 8);
    const uint32_t smb = smem_u32(sm);
    const uint32_t full_a  = smem_u32(mb_full);
    const uint32_t empty_a = smem_u32(mb_empty);

    if (tid == 0) {
#pragma unroll
        for (int s = 0; s < NSTAGE; s++) {
            MBAR_INIT(full_a + 8u * s, NT);    // all 256 threads' cp.async arrivals
            MBAR_INIT(empty_a + 8u * s, 8);    // one arrive per warp
        }
    }
    __syncthreads();

    // Strength-reduced copy addressing:
    // A copy i (i=0..3): mod=i, row=tid>>3, seg=tid&7 (BM=32, NT=256)
    // W copy i:          row=(tid>>3)+32*i, seg=tid&7
    const int arow = tid >> 3, aseg = tid & 7;
    const __half* __restrict__ srcA0 = &g_A[0][b0 + arow][aseg * 8];
    const __half* __restrict__ srcW0 = &g_W[k0 + arow][aseg * 8];
    const uint32_t dstA0 = 2u * (uint32_t)(arow * STRIDE + aseg * 8);
    const uint32_t dstW0 = 2u * (uint32_t)(W_OFFH + arow * STRIDE + aseg * 8);
    const uint32_t dstStep = 2u * (uint32_t)(32 * STRIDE);       // per-i dst stride
    const size_t srcAStep = (size_t)B_SZ * L_SZ;                 // per-i A src stride (mod)
    const size_t srcWStep = (size_t)32 * L_SZ;                   // per-i W src stride (rows)

    // Per-warp consumer base offsets (compile-time strides off stage bases)
    const uint32_t bOffW = 2u * (uint32_t)(W_OFFH + (wn * 32) * STRIDE) + 2u * laneB;
    const uint32_t aOffA = 2u * (uint32_t)((wm * 16) * STRIDE) + 2u * laneA;

    float acc[4][4][4];   // [mod][n8-tile][frag]
#pragma unroll
    for (int m = 0; m < 4; m++)
#pragma unroll
        for (int nt = 0; nt < 4; nt++)
#pragma unroll
            for (int c = 0; c < 4; c++) acc[m][nt][c] = 0.0f;

    auto issue = [&](int c, int s) {
        const uint32_t buf = smb + (uint32_t)(s * STG_HALVES) * 2u;
        const __half* sA = srcA0 + c * BK;
        const __half* sW = srcW0 + c * BK;
#pragma unroll
        for (int i = 0; i < 4; i++)
            CP16(buf + dstA0 + (uint32_t)i * dstStep, sA + (size_t)i * srcAStep);
#pragma unroll
        for (int i = 0; i < 4; i++)
            CP16(buf + dstW0 + (uint32_t)i * dstStep, sW + (size_t)i * srcWStep);
        CP_MBAR_ARRIVE(full_a + 8u * s);
    };

    issue(0, 0);
    issue(1, 1);

#pragma unroll
    for (int c = 0; c < NCHUNK; ++c) {
        const int s = c % NSTAGE;          // compile-time under full unroll
        const int rr = c / NSTAGE;

        MBAR_WAIT(full_a + 8u * s, rr & 1);
        const uint32_t buf = smb + (uint32_t)(s * STG_HALVES) * 2u;

#pragma unroll
        for (int half = 0; half < 2; half++) {
            if (half == 1) {
                // produce chunk c+2 between the two MMA halves
                const int cc = c + 2;
                if (cc < NCHUNK) {
                    const int s2 = cc % NSTAGE;
                    const int r2 = cc / NSTAGE;
                    if (r2 > 0) MBAR_WAIT_RLX(empty_a + 8u * s2, (r2 - 1) & 1);
                    issue(cc, s2);
                }
            }
#pragma unroll
            for (int kq = 0; kq < 2; kq++) {
                const int ks = half * 2 + kq;
                uint32_t B[8];
                const uint32_t bBase = buf + bOffW + 2u * (uint32_t)(ks * 16);
#pragma unroll
                for (int t = 0; t < 2; t++)
                    LDSM4(B[4 * t], B[4 * t + 1], B[4 * t + 2], B[4 * t + 3],
                          bBase + 2u * (uint32_t)(t * 16 * STRIDE));
#pragma unroll
                for (int m = 0; m < 4; m++) {
                    const uint32_t aBase =
                        buf + aOffA + 2u * (uint32_t)(m * BM * STRIDE + ks * 16);
                    uint32_t A0, A1, A2, A3;
                    LDSM4(A0, A1, A2, A3, aBase);
                    if (ks == 3 && m == 3) {
                        // nt=3 first: consumes A0..A3 and B[6..7]; B[0..5] proven
                        // complete by earlier m-groups -> safe to release stage.
                        MMA16816(acc[3][3], A0, A1, A2, A3, B[6], B[7]);
                        if (lane == 0) MBAR_ARRIVE(empty_a + 8u * s);
#pragma unroll
                        for (int nt = 0; nt < 3; nt++)
                            MMA16816(acc[3][nt], A0, A1, A2, A3, B[nt * 2], B[nt * 2 + 1]);
                    } else {
#pragma unroll
                        for (int nt = 0; nt < 4; nt++)
                            MMA16816(acc[m][nt], A0, A1, A2, A3, B[nt * 2], B[nt * 2 + 1]);
                    }
                }
            }
        }
    }

    // ---- epilogue: softmax over modalities + weighted sum + rescale ----
    const int qr = lane >> 2;
    const int qc = (lane & 3) * 2;
#pragma unroll
    for (int rp = 0; rp < 2; rp++) {
        const int row = wm * 16 + qr + rp * 8;
        const float sc_row = g_scal[b0 + row];
        const size_t g = (size_t)(b0 + row) * L_SZ + k0 + wn * 32;
#pragma unroll
        for (int nt = 0; nt < 4; nt++) {
            float2 x[4];
#pragma unroll
            for (int m = 0; m < 4; m++)
                x[m] = *(const float2*)(mods[m] + g + nt * 8 + qc);
            float res[2];
#pragma unroll
            for (int cc2 = 0; cc2 < 2; cc2++) {
                const float s0 = acc[0][nt][rp * 2 + cc2];
                const float s1 = acc[1][nt][rp * 2 + cc2];
                const float s2 = acc[2][nt][rp * 2 + cc2];
                const float s3 = acc[3][nt][rp * 2 + cc2];
                const float mx = fmaxf(fmaxf(s0, s1), fmaxf(s2, s3));
                const float e0 = __expf(s0 - mx);
                const float e1 = __expf(s1 - mx);
                const float e2 = __expf(s2 - mx);
                const float e3 = __expf(s3 - mx);
                const float inv = 1.0f / (e0 + e1 + e2 + e3);
                const float x0 = cc2 ? x[0].y : x[0].x;
                const float x1 = cc2 ? x[1].y : x[1].x;
                const float x2 = cc2 ? x[2].y : x[2].x;
                const float x3 = cc2 ? x[3].y : x[3].x;
                res[cc2] = (e0 * x0 + e1 * x1 + e2 * x2 + e3 * x3) * inv * sc_row;
            }
            *(float2*)(out + g + nt * 8 + qc) = make_float2(res[0], res[1]);
        }
    }
}

extern "C" void kernel_launch(void* const* d_in, const int* in_sizes, int n_in,
                              void* d_out, int out_size)
{
    const float* mods[4] = {nullptr, nullptr, nullptr, nullptr};
    const float* W = nullptr;
    int mi = 0;
    for (int i = 0; i < n_in; i++) {
        if (in_sizes[i] == L_SZ * L_SZ) W = (const float*)d_in[i];
        else if (mi < 4) mods[mi++] = (const float*)d_in[i];
    }
    if (!W) W = (const float*)d_in[n_in - 1];

    cudaFuncSetAttribute(fused_modal_attn_hmma,
                         cudaFuncAttributeMaxDynamicSharedMemorySize, SMEM_BYTES);

    prep_kernel<<<B_SZ + L_SZ, 128>>>(mods[0], mods[1], mods[2], mods[3], W);

    dim3 grid(L_SZ / BN, B_SZ / BM);   // (8, 512): k-tiles fastest -> A L2-coresident
    fused_modal_attn_hmma<<<grid, NT, SMEM_BYTES>>>(
        mods[0], mods[1], mods[2], mods[3], (float*)d_out);
}